// round 12
// baseline (speedup 1.0000x reference)
#include <cuda_runtime.h>
#include <math.h>

#define BS   2
#define SEQ  2048
#define DM   1024
#define NH   16
#define DQ   64
#define BHN  (BS*NH)
#define NEG_INF (-1e30f)

// ---------------- scratch (device globals: no allocations allowed) ----------------
__device__ float g_q[(size_t)BHN*SEQ*DQ];   // [b,h,s,d]
__device__ float g_k[(size_t)BHN*SEQ*DQ];
__device__ float g_v[(size_t)BHN*SEQ*DQ];
__device__ float g_o[(size_t)BHN*SEQ*DQ];   // attention output per head
__device__ float g_y[(size_t)BS*SEQ*DM];    // fc output before LN
__device__ float g_m[(size_t)BHN*SEQ];      // row max of scores
__device__ float g_l[(size_t)BHN*SEQ];      // row sum of exp(s - m)

// ---------------- projection GEMM: C[m,e] = sum_k X[m,k] * W[e,k] ----------------
// X: [4096,1024] row-major, W: [1024,1024] row-major ([out,in]).
// Writes to g_q/g_k/g_v in [b,h,s,d] layout. 128x128 tile, BK=16, 256 thr, 8x8/thr.
__global__ void __launch_bounds__(256) proj_kernel(const float* __restrict__ X,
                                                   const float* __restrict__ W,
                                                   int which)
{
    float* out = (which == 0) ? g_q : (which == 1) ? g_k : g_v;
    __shared__ float As[16][132];
    __shared__ float Bs[16][132];
    const int tid = threadIdx.x;
    const int tx = tid & 15, ty = tid >> 4;
    const int m0 = blockIdx.y * 128, n0 = blockIdx.x * 128;
    const int lr = tid >> 2;          // 0..63 (two passes: +0, +64)
    const int lc = (tid & 3) << 2;    // 0,4,8,12

    float acc[8][8];
    #pragma unroll
    for (int i = 0; i < 8; i++)
        #pragma unroll
        for (int j = 0; j < 8; j++) acc[i][j] = 0.f;

    for (int k0 = 0; k0 < DM; k0 += 16) {
        #pragma unroll
        for (int i = 0; i < 2; i++) {
            int r = lr + 64*i;
            float4 va = *(const float4*)(X + (size_t)(m0 + r)*DM + k0 + lc);
            As[lc+0][r] = va.x; As[lc+1][r] = va.y;
            As[lc+2][r] = va.z; As[lc+3][r] = va.w;
            float4 vb = *(const float4*)(W + (size_t)(n0 + r)*DM + k0 + lc);
            Bs[lc+0][r] = vb.x; Bs[lc+1][r] = vb.y;
            Bs[lc+2][r] = vb.z; Bs[lc+3][r] = vb.w;
        }
        __syncthreads();
        #pragma unroll
        for (int k = 0; k < 16; k++) {
            float a[8], b[8];
            *(float4*)(a)     = *(const float4*)&As[k][ty*8];
            *(float4*)(a + 4) = *(const float4*)&As[k][ty*8 + 4];
            *(float4*)(b)     = *(const float4*)&Bs[k][tx*8];
            *(float4*)(b + 4) = *(const float4*)&Bs[k][tx*8 + 4];
            #pragma unroll
            for (int i = 0; i < 8; i++)
                #pragma unroll
                for (int j = 0; j < 8; j++)
                    acc[i][j] = fmaf(a[i], b[j], acc[i][j]);
        }
        __syncthreads();
    }
    // epilogue: scatter to [b,h,s,d]
    #pragma unroll
    for (int i = 0; i < 8; i++) {
        int m = m0 + ty*8 + i;
        int b = m >> 11, s = m & (SEQ - 1);
        #pragma unroll
        for (int j = 0; j < 8; j += 4) {
            int e = n0 + tx*8 + j;
            int h = e >> 6, d = e & 63;
            float4 v = make_float4(acc[i][j], acc[i][j+1], acc[i][j+2], acc[i][j+3]);
            *(float4*)(out + (((size_t)(b*NH + h)*SEQ + s)*DQ + d)) = v;
        }
    }
}

// ---------------- fc GEMM: y[m,n] = sum_e O[m,e] * Wfc[n,e] ----------------
// O gathered from g_o's [b,h,s,d] layout; writes g_y [4096,1024] row-major.
__global__ void __launch_bounds__(256) fc_kernel(const float* __restrict__ Wfc)
{
    __shared__ float As[16][132];
    __shared__ float Bs[16][132];
    const int tid = threadIdx.x;
    const int tx = tid & 15, ty = tid >> 4;
    const int m0 = blockIdx.y * 128, n0 = blockIdx.x * 128;
    const int lr = tid >> 2;
    const int lc = (tid & 3) << 2;

    float acc[8][8];
    #pragma unroll
    for (int i = 0; i < 8; i++)
        #pragma unroll
        for (int j = 0; j < 8; j++) acc[i][j] = 0.f;

    for (int k0 = 0; k0 < DM; k0 += 16) {
        int e = k0 + lc;
        int h = e >> 6, d = e & 63;
        #pragma unroll
        for (int i = 0; i < 2; i++) {
            int r = lr + 64*i;
            int m = m0 + r;
            int b = m >> 11, s = m & (SEQ - 1);
            float4 va = *(const float4*)(g_o + ((size_t)(b*NH + h)*SEQ + s)*DQ + d);
            As[lc+0][r] = va.x; As[lc+1][r] = va.y;
            As[lc+2][r] = va.z; As[lc+3][r] = va.w;
            float4 vb = *(const float4*)(Wfc + (size_t)(n0 + r)*DM + k0 + lc);
            Bs[lc+0][r] = vb.x; Bs[lc+1][r] = vb.y;
            Bs[lc+2][r] = vb.z; Bs[lc+3][r] = vb.w;
        }
        __syncthreads();
        #pragma unroll
        for (int k = 0; k < 16; k++) {
            float a[8], b[8];
            *(float4*)(a)     = *(const float4*)&As[k][ty*8];
            *(float4*)(a + 4) = *(const float4*)&As[k][ty*8 + 4];
            *(float4*)(b)     = *(const float4*)&Bs[k][tx*8];
            *(float4*)(b + 4) = *(const float4*)&Bs[k][tx*8 + 4];
            #pragma unroll
            for (int i = 0; i < 8; i++)
                #pragma unroll
                for (int j = 0; j < 8; j++)
                    acc[i][j] = fmaf(a[i], b[j], acc[i][j]);
        }
        __syncthreads();
    }
    #pragma unroll
    for (int i = 0; i < 8; i++) {
        int m = m0 + ty*8 + i;
        #pragma unroll
        for (int j = 0; j < 8; j += 4) {
            float4 v = make_float4(acc[i][j], acc[i][j+1], acc[i][j+2], acc[i][j+3]);
            *(float4*)(g_y + (size_t)m*DM + n0 + tx*8 + j) = v;
        }
    }
}

// ---------------- scores: S = Q K^T, raw scores -> a-region, online (m,l) ----------
// grid (SEQ/64, BHN). CTA: 64 q-rows x all 2048 kv. 256 thr, 4x4/thr on 64x64 tiles.
__global__ void __launch_bounds__(256) scores_kernel(float* __restrict__ a_out)
{
    const int bh = blockIdx.y;
    const int q0 = blockIdx.x * 64;
    const float* Qp = g_q + (size_t)bh*SEQ*DQ;
    const float* Kp = g_k + (size_t)bh*SEQ*DQ;
    float* Sp = a_out + (size_t)bh*SEQ*SEQ;

    __shared__ float Qs[64][68];   // [k][q]
    __shared__ float Ks[64][68];   // [k][kv]
    const int tid = threadIdx.x;
    const int tx = tid & 15, ty = tid >> 4;
    const int lr = tid >> 4;          // 0..15
    const int lc = (tid & 15) << 2;   // 0..60

    #pragma unroll
    for (int i = 0; i < 4; i++) {
        int r = lr + 16*i;
        float4 v = *(const float4*)(Qp + (size_t)(q0 + r)*DQ + lc);
        Qs[lc+0][r] = v.x; Qs[lc+1][r] = v.y; Qs[lc+2][r] = v.z; Qs[lc+3][r] = v.w;
    }

    float run_m[4], run_l[4];
    #pragma unroll
    for (int i = 0; i < 4; i++) { run_m[i] = NEG_INF; run_l[i] = 0.f; }

    for (int kv0 = 0; kv0 < SEQ; kv0 += 64) {
        #pragma unroll
        for (int i = 0; i < 4; i++) {
            int r = lr + 16*i;
            float4 v = *(const float4*)(Kp + (size_t)(kv0 + r)*DQ + lc);
            Ks[lc+0][r] = v.x; Ks[lc+1][r] = v.y; Ks[lc+2][r] = v.z; Ks[lc+3][r] = v.w;
        }
        __syncthreads();

        float s[4][4];
        #pragma unroll
        for (int i = 0; i < 4; i++)
            #pragma unroll
            for (int j = 0; j < 4; j++) s[i][j] = 0.f;

        #pragma unroll 16
        for (int k = 0; k < 64; k++) {
            float a[4], b[4];
            *(float4*)a = *(const float4*)&Qs[k][ty*4];
            *(float4*)b = *(const float4*)&Ks[k][tx*4];
            #pragma unroll
            for (int i = 0; i < 4; i++)
                #pragma unroll
                for (int j = 0; j < 4; j++)
                    s[i][j] = fmaf(a[i], b[j], s[i][j]);
        }

        // exact online max/sumexp per row (butterfly over the 16 tx lanes)
        #pragma unroll
        for (int i = 0; i < 4; i++) {
            float tmax = fmaxf(fmaxf(s[i][0], s[i][1]), fmaxf(s[i][2], s[i][3]));
            #pragma unroll
            for (int o = 8; o; o >>= 1)
                tmax = fmaxf(tmax, __shfl_xor_sync(0xffffffffu, tmax, o));
            float nm = fmaxf(run_m[i], tmax);
            float tsum = __expf(s[i][0] - nm) + __expf(s[i][1] - nm)
                       + __expf(s[i][2] - nm) + __expf(s[i][3] - nm);
            #pragma unroll
            for (int o = 8; o; o >>= 1)
                tsum += __shfl_xor_sync(0xffffffffu, tsum, o);
            run_l[i] = run_l[i] * __expf(run_m[i] - nm) + tsum;
            run_m[i] = nm;
        }

        // store raw scores
        #pragma unroll
        for (int i = 0; i < 4; i++) {
            float4 v = make_float4(s[i][0], s[i][1], s[i][2], s[i][3]);
            *(float4*)(Sp + (size_t)(q0 + ty*4 + i)*SEQ + kv0 + tx*4) = v;
        }
        __syncthreads();
    }

    if (tx == 0) {
        #pragma unroll
        for (int i = 0; i < 4; i++) {
            g_m[(size_t)bh*SEQ + q0 + ty*4 + i] = run_m[i];
            g_l[(size_t)bh*SEQ + q0 + ty*4 + i] = run_l[i];
        }
    }
}

// ---------------- AV: normalize probs in-place + O = P V ----------------
// grid (SEQ/64, BHN). CTA: 64 q-rows x 64 d-cols, loop kv tiles of 64.
__global__ void __launch_bounds__(256) av_kernel(float* __restrict__ a_out)
{
    const int bh = blockIdx.y;
    const int q0 = blockIdx.x * 64;
    const float* Vp = g_v + (size_t)bh*SEQ*DQ;
    float* Sp = a_out + (size_t)bh*SEQ*SEQ;

    __shared__ float Ps[64][68];   // [kv][q]
    __shared__ float Vs[64][68];   // [kv][d]
    __shared__ float sm_m[64], sm_il[64];
    const int tid = threadIdx.x;
    const int tx = tid & 15, ty = tid >> 4;
    const int lr = tid >> 4;
    const int lc = (tid & 15) << 2;

    if (tid < 64) {
        sm_m[tid]  = g_m[(size_t)bh*SEQ + q0 + tid];
        sm_il[tid] = 1.0f / g_l[(size_t)bh*SEQ + q0 + tid];
    }
    __syncthreads();

    float acc[4][4];
    #pragma unroll
    for (int i = 0; i < 4; i++)
        #pragma unroll
        for (int j = 0; j < 4; j++) acc[i][j] = 0.f;

    for (int kv0 = 0; kv0 < SEQ; kv0 += 64) {
        #pragma unroll
        for (int i = 0; i < 4; i++) {
            int r = lr + 16*i;
            float* sp = Sp + (size_t)(q0 + r)*SEQ + kv0 + lc;
            float4 v = *(const float4*)sp;
            float m = sm_m[r], il = sm_il[r];
            float4 p;
            p.x = __expf(v.x - m) * il;
            p.y = __expf(v.y - m) * il;
            p.z = __expf(v.z - m) * il;
            p.w = __expf(v.w - m) * il;
            *(float4*)sp = p;                       // final attention probs
            Ps[lc+0][r] = p.x; Ps[lc+1][r] = p.y;
            Ps[lc+2][r] = p.z; Ps[lc+3][r] = p.w;
            float4 w = *(const float4*)(Vp + (size_t)(kv0 + r)*DQ + lc);
            *(float4*)&Vs[r][lc] = w;
        }
        __syncthreads();

        #pragma unroll 16
        for (int k = 0; k < 64; k++) {
            float a[4], b[4];
            *(float4*)a = *(const float4*)&Ps[k][ty*4];
            *(float4*)b = *(const float4*)&Vs[k][tx*4];
            #pragma unroll
            for (int i = 0; i < 4; i++)
                #pragma unroll
                for (int j = 0; j < 4; j++)
                    acc[i][j] = fmaf(a[i], b[j], acc[i][j]);
        }
        __syncthreads();
    }

    #pragma unroll
    for (int i = 0; i < 4; i++) {
        float4 v = make_float4(acc[i][0], acc[i][1], acc[i][2], acc[i][3]);
        *(float4*)(g_o + ((size_t)bh*SEQ + q0 + ty*4 + i)*DQ + tx*4) = v;
    }
}

// ---------------- residual + LayerNorm ----------------
// grid 4096 rows, 256 thr; each thread owns 4 contiguous floats.
__global__ void __launch_bounds__(256) ln_kernel(const float* __restrict__ xq,
                                                 float* __restrict__ out)
{
    const int r = blockIdx.x;
    const int t = threadIdx.x;
    float4 a = ((const float4*)(g_y + (size_t)r*DM))[t];
    float4 b = ((const float4*)(xq  + (size_t)r*DM))[t];
    float z0 = a.x + b.x, z1 = a.y + b.y, z2 = a.z + b.z, z3 = a.w + b.w;
    float s = z0 + z1 + z2 + z3;
    float q = z0*z0 + z1*z1 + z2*z2 + z3*z3;

    __shared__ float red[2][8];
    #pragma unroll
    for (int o = 16; o; o >>= 1) {
        s += __shfl_xor_sync(0xffffffffu, s, o);
        q += __shfl_xor_sync(0xffffffffu, q, o);
    }
    int w = t >> 5, l = t & 31;
    if (l == 0) { red[0][w] = s; red[1][w] = q; }
    __syncthreads();
    float S = 0.f, Q = 0.f;
    #pragma unroll
    for (int i = 0; i < 8; i++) { S += red[0][i]; Q += red[1][i]; }
    float mu  = S * (1.0f / DM);
    float var = Q * (1.0f / DM) - mu * mu;
    float inv = rsqrtf(var + 1e-5f);
    float4 o;
    o.x = (z0 - mu) * inv; o.y = (z1 - mu) * inv;
    o.z = (z2 - mu) * inv; o.w = (z3 - mu) * inv;
    ((float4*)(out + (size_t)r*DM))[t] = o;
}

// ---------------- launch ----------------
extern "C" void kernel_launch(void* const* d_in, const int* in_sizes, int n_in,
                              void* d_out, int out_size)
{
    (void)in_sizes; (void)n_in; (void)out_size;
    const float* xq  = (const float*)d_in[0];
    const float* xk  = (const float*)d_in[1];
    const float* xv  = (const float*)d_in[2];
    const float* WQ  = (const float*)d_in[3];
    const float* WK  = (const float*)d_in[4];
    const float* WV  = (const float*)d_in[5];
    const float* Wfc = (const float*)d_in[6];

    float* a_out = (float*)d_out;                                  // [2,16,2048,2048]
    float* o_out = (float*)d_out + (size_t)BHN*SEQ*SEQ;            // [2,2048,1024]

    dim3 pg(DM/128, (BS*SEQ)/128);   // (8, 32)
    dim3 ag(SEQ/64, BHN);            // (32, 32)

    proj_kernel<<<pg, 256>>>(xq, WQ, 0);
    proj_kernel<<<pg, 256>>>(xk, WK, 1);
    proj_kernel<<<pg, 256>>>(xv, WV, 2);
    scores_kernel<<<ag, 256>>>(a_out);
    av_kernel<<<ag, 256>>>(a_out);
    fc_kernel<<<pg, 256>>>(Wfc);
    ln_kernel<<<BS*SEQ, 256>>>(xq, o_out);
}

// round 13
// speedup vs baseline: 1.0009x; 1.0009x over previous
#include <cuda_runtime.h>
#include <math.h>

#define BS   2
#define SEQ  2048
#define DM   1024
#define NH   16
#define DQ   64
#define BHN  (BS*NH)
#define NEG_INF (-1e30f)

// ---------------- scratch (device globals: no allocations allowed) ----------------
__device__ float g_q[(size_t)BHN*SEQ*DQ];   // [b,h,s,d]
__device__ float g_k[(size_t)BHN*SEQ*DQ];
__device__ float g_v[(size_t)BHN*SEQ*DQ];
__device__ float g_o[(size_t)BHN*SEQ*DQ];   // attention output per head
__device__ float g_y[(size_t)BS*SEQ*DM];    // fc output before LN
__device__ float g_m[(size_t)BHN*SEQ];      // row max of scores
__device__ float g_l[(size_t)BHN*SEQ];      // row sum of exp(s - m)

// ---------------- projection GEMM: C[m,e] = sum_k X[m,k] * W[e,k] ----------------
// X: [4096,1024] row-major, W: [1024,1024] row-major ([out,in]).
// Writes to g_q/g_k/g_v in [b,h,s,d] layout. 128x128 tile, BK=16, 256 thr, 8x8/thr.
__global__ void __launch_bounds__(256) proj_kernel(const float* __restrict__ X,
                                                   const float* __restrict__ W,
                                                   int which)
{
    float* out = (which == 0) ? g_q : (which == 1) ? g_k : g_v;
    __shared__ float As[16][132];
    __shared__ float Bs[16][132];
    const int tid = threadIdx.x;
    const int tx = tid & 15, ty = tid >> 4;
    const int m0 = blockIdx.y * 128, n0 = blockIdx.x * 128;
    const int lr = tid >> 2;          // 0..63 (two passes: +0, +64)
    const int lc = (tid & 3) << 2;    // 0,4,8,12

    float acc[8][8];
    #pragma unroll
    for (int i = 0; i < 8; i++)
        #pragma unroll
        for (int j = 0; j < 8; j++) acc[i][j] = 0.f;

    for (int k0 = 0; k0 < DM; k0 += 16) {
        #pragma unroll
        for (int i = 0; i < 2; i++) {
            int r = lr + 64*i;
            float4 va = *(const float4*)(X + (size_t)(m0 + r)*DM + k0 + lc);
            As[lc+0][r] = va.x; As[lc+1][r] = va.y;
            As[lc+2][r] = va.z; As[lc+3][r] = va.w;
            float4 vb = *(const float4*)(W + (size_t)(n0 + r)*DM + k0 + lc);
            Bs[lc+0][r] = vb.x; Bs[lc+1][r] = vb.y;
            Bs[lc+2][r] = vb.z; Bs[lc+3][r] = vb.w;
        }
        __syncthreads();
        #pragma unroll
        for (int k = 0; k < 16; k++) {
            float a[8], b[8];
            *(float4*)(a)     = *(const float4*)&As[k][ty*8];
            *(float4*)(a + 4) = *(const float4*)&As[k][ty*8 + 4];
            *(float4*)(b)     = *(const float4*)&Bs[k][tx*8];
            *(float4*)(b + 4) = *(const float4*)&Bs[k][tx*8 + 4];
            #pragma unroll
            for (int i = 0; i < 8; i++)
                #pragma unroll
                for (int j = 0; j < 8; j++)
                    acc[i][j] = fmaf(a[i], b[j], acc[i][j]);
        }
        __syncthreads();
    }
    // epilogue: scatter to [b,h,s,d]
    #pragma unroll
    for (int i = 0; i < 8; i++) {
        int m = m0 + ty*8 + i;
        int b = m >> 11, s = m & (SEQ - 1);
        #pragma unroll
        for (int j = 0; j < 8; j += 4) {
            int e = n0 + tx*8 + j;
            int h = e >> 6, d = e & 63;
            float4 v = make_float4(acc[i][j], acc[i][j+1], acc[i][j+2], acc[i][j+3]);
            *(float4*)(out + (((size_t)(b*NH + h)*SEQ + s)*DQ + d)) = v;
        }
    }
}

// ---------------- fc GEMM: y[m,n] = sum_e O[m,e] * Wfc[n,e] ----------------
// O gathered from g_o's [b,h,s,d] layout; writes g_y [4096,1024] row-major.
__global__ void __launch_bounds__(256) fc_kernel(const float* __restrict__ Wfc)
{
    __shared__ float As[16][132];
    __shared__ float Bs[16][132];
    const int tid = threadIdx.x;
    const int tx = tid & 15, ty = tid >> 4;
    const int m0 = blockIdx.y * 128, n0 = blockIdx.x * 128;
    const int lr = tid >> 2;
    const int lc = (tid & 3) << 2;

    float acc[8][8];
    #pragma unroll
    for (int i = 0; i < 8; i++)
        #pragma unroll
        for (int j = 0; j < 8; j++) acc[i][j] = 0.f;

    for (int k0 = 0; k0 < DM; k0 += 16) {
        int e = k0 + lc;
        int h = e >> 6, d = e & 63;
        #pragma unroll
        for (int i = 0; i < 2; i++) {
            int r = lr + 64*i;
            int m = m0 + r;
            int b = m >> 11, s = m & (SEQ - 1);
            float4 va = *(const float4*)(g_o + ((size_t)(b*NH + h)*SEQ + s)*DQ + d);
            As[lc+0][r] = va.x; As[lc+1][r] = va.y;
            As[lc+2][r] = va.z; As[lc+3][r] = va.w;
            float4 vb = *(const float4*)(Wfc + (size_t)(n0 + r)*DM + k0 + lc);
            Bs[lc+0][r] = vb.x; Bs[lc+1][r] = vb.y;
            Bs[lc+2][r] = vb.z; Bs[lc+3][r] = vb.w;
        }
        __syncthreads();
        #pragma unroll
        for (int k = 0; k < 16; k++) {
            float a[8], b[8];
            *(float4*)(a)     = *(const float4*)&As[k][ty*8];
            *(float4*)(a + 4) = *(const float4*)&As[k][ty*8 + 4];
            *(float4*)(b)     = *(const float4*)&Bs[k][tx*8];
            *(float4*)(b + 4) = *(const float4*)&Bs[k][tx*8 + 4];
            #pragma unroll
            for (int i = 0; i < 8; i++)
                #pragma unroll
                for (int j = 0; j < 8; j++)
                    acc[i][j] = fmaf(a[i], b[j], acc[i][j]);
        }
        __syncthreads();
    }
    #pragma unroll
    for (int i = 0; i < 8; i++) {
        int m = m0 + ty*8 + i;
        #pragma unroll
        for (int j = 0; j < 8; j += 4) {
            float4 v = make_float4(acc[i][j], acc[i][j+1], acc[i][j+2], acc[i][j+3]);
            *(float4*)(g_y + (size_t)m*DM + n0 + tx*8 + j) = v;
        }
    }
}

// ---------------- scores: S = Q K^T, raw scores -> a-region, online (m,l) ----------
// grid (SEQ/64, BHN). CTA: 64 q-rows x all 2048 kv. 256 thr, 4x4/thr on 64x64 tiles.
__global__ void __launch_bounds__(256) scores_kernel(float* __restrict__ a_out)
{
    const int bh = blockIdx.y;
    const int q0 = blockIdx.x * 64;
    const float* Qp = g_q + (size_t)bh*SEQ*DQ;
    const float* Kp = g_k + (size_t)bh*SEQ*DQ;
    float* Sp = a_out + (size_t)bh*SEQ*SEQ;

    __shared__ float Qs[64][68];   // [k][q]
    __shared__ float Ks[64][68];   // [k][kv]
    const int tid = threadIdx.x;
    const int tx = tid & 15, ty = tid >> 4;
    const int lr = tid >> 4;          // 0..15
    const int lc = (tid & 15) << 2;   // 0..60

    #pragma unroll
    for (int i = 0; i < 4; i++) {
        int r = lr + 16*i;
        float4 v = *(const float4*)(Qp + (size_t)(q0 + r)*DQ + lc);
        Qs[lc+0][r] = v.x; Qs[lc+1][r] = v.y; Qs[lc+2][r] = v.z; Qs[lc+3][r] = v.w;
    }

    float run_m[4], run_l[4];
    #pragma unroll
    for (int i = 0; i < 4; i++) { run_m[i] = NEG_INF; run_l[i] = 0.f; }

    for (int kv0 = 0; kv0 < SEQ; kv0 += 64) {
        #pragma unroll
        for (int i = 0; i < 4; i++) {
            int r = lr + 16*i;
            float4 v = *(const float4*)(Kp + (size_t)(kv0 + r)*DQ + lc);
            Ks[lc+0][r] = v.x; Ks[lc+1][r] = v.y; Ks[lc+2][r] = v.z; Ks[lc+3][r] = v.w;
        }
        __syncthreads();

        float s[4][4];
        #pragma unroll
        for (int i = 0; i < 4; i++)
            #pragma unroll
            for (int j = 0; j < 4; j++) s[i][j] = 0.f;

        #pragma unroll 16
        for (int k = 0; k < 64; k++) {
            float a[4], b[4];
            *(float4*)a = *(const float4*)&Qs[k][ty*4];
            *(float4*)b = *(const float4*)&Ks[k][tx*4];
            #pragma unroll
            for (int i = 0; i < 4; i++)
                #pragma unroll
                for (int j = 0; j < 4; j++)
                    s[i][j] = fmaf(a[i], b[j], s[i][j]);
        }

        // exact online max/sumexp per row (butterfly over the 16 tx lanes)
        #pragma unroll
        for (int i = 0; i < 4; i++) {
            float tmax = fmaxf(fmaxf(s[i][0], s[i][1]), fmaxf(s[i][2], s[i][3]));
            #pragma unroll
            for (int o = 8; o; o >>= 1)
                tmax = fmaxf(tmax, __shfl_xor_sync(0xffffffffu, tmax, o));
            float nm = fmaxf(run_m[i], tmax);
            float tsum = __expf(s[i][0] - nm) + __expf(s[i][1] - nm)
                       + __expf(s[i][2] - nm) + __expf(s[i][3] - nm);
            #pragma unroll
            for (int o = 8; o; o >>= 1)
                tsum += __shfl_xor_sync(0xffffffffu, tsum, o);
            run_l[i] = run_l[i] * __expf(run_m[i] - nm) + tsum;
            run_m[i] = nm;
        }

        // store raw scores
        #pragma unroll
        for (int i = 0; i < 4; i++) {
            float4 v = make_float4(s[i][0], s[i][1], s[i][2], s[i][3]);
            *(float4*)(Sp + (size_t)(q0 + ty*4 + i)*SEQ + kv0 + tx*4) = v;
        }
        __syncthreads();
    }

    if (tx == 0) {
        #pragma unroll
        for (int i = 0; i < 4; i++) {
            g_m[(size_t)bh*SEQ + q0 + ty*4 + i] = run_m[i];
            g_l[(size_t)bh*SEQ + q0 + ty*4 + i] = run_l[i];
        }
    }
}

// ---------------- AV: normalize probs in-place + O = P V ----------------
// grid (SEQ/64, BHN). CTA: 64 q-rows x 64 d-cols, loop kv tiles of 64.
__global__ void __launch_bounds__(256) av_kernel(float* __restrict__ a_out)
{
    const int bh = blockIdx.y;
    const int q0 = blockIdx.x * 64;
    const float* Vp = g_v + (size_t)bh*SEQ*DQ;
    float* Sp = a_out + (size_t)bh*SEQ*SEQ;

    __shared__ float Ps[64][68];   // [kv][q]
    __shared__ float Vs[64][68];   // [kv][d]
    __shared__ float sm_m[64], sm_il[64];
    const int tid = threadIdx.x;
    const int tx = tid & 15, ty = tid >> 4;
    const int lr = tid >> 4;
    const int lc = (tid & 15) << 2;

    if (tid < 64) {
        sm_m[tid]  = g_m[(size_t)bh*SEQ + q0 + tid];
        sm_il[tid] = 1.0f / g_l[(size_t)bh*SEQ + q0 + tid];
    }
    __syncthreads();

    float acc[4][4];
    #pragma unroll
    for (int i = 0; i < 4; i++)
        #pragma unroll
        for (int j = 0; j < 4; j++) acc[i][j] = 0.f;

    for (int kv0 = 0; kv0 < SEQ; kv0 += 64) {
        #pragma unroll
        for (int i = 0; i < 4; i++) {
            int r = lr + 16*i;
            float* sp = Sp + (size_t)(q0 + r)*SEQ + kv0 + lc;
            float4 v = *(const float4*)sp;
            float m = sm_m[r], il = sm_il[r];
            float4 p;
            p.x = __expf(v.x - m) * il;
            p.y = __expf(v.y - m) * il;
            p.z = __expf(v.z - m) * il;
            p.w = __expf(v.w - m) * il;
            *(float4*)sp = p;                       // final attention probs
            Ps[lc+0][r] = p.x; Ps[lc+1][r] = p.y;
            Ps[lc+2][r] = p.z; Ps[lc+3][r] = p.w;
            float4 w = *(const float4*)(Vp + (size_t)(kv0 + r)*DQ + lc);
            *(float4*)&Vs[r][lc] = w;
        }
        __syncthreads();

        #pragma unroll 16
        for (int k = 0; k < 64; k++) {
            float a[4], b[4];
            *(float4*)a = *(const float4*)&Ps[k][ty*4];
            *(float4*)b = *(const float4*)&Vs[k][tx*4];
            #pragma unroll
            for (int i = 0; i < 4; i++)
                #pragma unroll
                for (int j = 0; j < 4; j++)
                    acc[i][j] = fmaf(a[i], b[j], acc[i][j]);
        }
        __syncthreads();
    }

    #pragma unroll
    for (int i = 0; i < 4; i++) {
        float4 v = make_float4(acc[i][0], acc[i][1], acc[i][2], acc[i][3]);
        *(float4*)(g_o + ((size_t)bh*SEQ + q0 + ty*4 + i)*DQ + tx*4) = v;
    }
}

// ---------------- residual + LayerNorm ----------------
// grid 4096 rows, 256 thr; each thread owns 4 contiguous floats.
__global__ void __launch_bounds__(256) ln_kernel(const float* __restrict__ xq,
                                                 float* __restrict__ out)
{
    const int r = blockIdx.x;
    const int t = threadIdx.x;
    float4 a = ((const float4*)(g_y + (size_t)r*DM))[t];
    float4 b = ((const float4*)(xq  + (size_t)r*DM))[t];
    float z0 = a.x + b.x, z1 = a.y + b.y, z2 = a.z + b.z, z3 = a.w + b.w;
    float s = z0 + z1 + z2 + z3;
    float q = z0*z0 + z1*z1 + z2*z2 + z3*z3;

    __shared__ float red[2][8];
    #pragma unroll
    for (int o = 16; o; o >>= 1) {
        s += __shfl_xor_sync(0xffffffffu, s, o);
        q += __shfl_xor_sync(0xffffffffu, q, o);
    }
    int w = t >> 5, l = t & 31;
    if (l == 0) { red[0][w] = s; red[1][w] = q; }
    __syncthreads();
    float S = 0.f, Q = 0.f;
    #pragma unroll
    for (int i = 0; i < 8; i++) { S += red[0][i]; Q += red[1][i]; }
    float mu  = S * (1.0f / DM);
    float var = Q * (1.0f / DM) - mu * mu;
    float inv = rsqrtf(var + 1e-5f);
    float4 o;
    o.x = (z0 - mu) * inv; o.y = (z1 - mu) * inv;
    o.z = (z2 - mu) * inv; o.w = (z3 - mu) * inv;
    ((float4*)(out + (size_t)r*DM))[t] = o;
}

// ---------------- launch ----------------
extern "C" void kernel_launch(void* const* d_in, const int* in_sizes, int n_in,
                              void* d_out, int out_size)
{
    (void)in_sizes; (void)n_in; (void)out_size;
    const float* xq  = (const float*)d_in[0];
    const float* xk  = (const float*)d_in[1];
    const float* xv  = (const float*)d_in[2];
    const float* WQ  = (const float*)d_in[3];
    const float* WK  = (const float*)d_in[4];
    const float* WV  = (const float*)d_in[5];
    const float* Wfc = (const float*)d_in[6];

    float* a_out = (float*)d_out;                                  // [2,16,2048,2048]
    float* o_out = (float*)d_out + (size_t)BHN*SEQ*SEQ;            // [2,2048,1024]

    dim3 pg(DM/128, (BS*SEQ)/128);   // (8, 32)
    dim3 ag(SEQ/64, BHN);            // (32, 32)

    proj_kernel<<<pg, 256>>>(xq, WQ, 0);
    proj_kernel<<<pg, 256>>>(xk, WK, 1);
    proj_kernel<<<pg, 256>>>(xv, WV, 2);
    scores_kernel<<<ag, 256>>>(a_out);
    av_kernel<<<ag, 256>>>(a_out);
    fc_kernel<<<pg, 256>>>(Wfc);
    ln_kernel<<<BS*SEQ, 256>>>(xq, o_out);
}

// round 14
// speedup vs baseline: 1.0022x; 1.0013x over previous
#include <cuda_runtime.h>
#include <math.h>

#define BS   2
#define SEQ  2048
#define DM   1024
#define NH   16
#define DQ   64
#define BHN  (BS*NH)
#define NEG_INF (-1e30f)

// ---------------- scratch (device globals: no allocations allowed) ----------------
__device__ float g_q[(size_t)BHN*SEQ*DQ];   // [b,h,s,d]
__device__ float g_k[(size_t)BHN*SEQ*DQ];
__device__ float g_v[(size_t)BHN*SEQ*DQ];
__device__ float g_o[(size_t)BHN*SEQ*DQ];   // attention output per head
__device__ float g_y[(size_t)BS*SEQ*DM];    // fc output before LN
__device__ float g_m[(size_t)BHN*SEQ];      // row max of scores
__device__ float g_l[(size_t)BHN*SEQ];      // row sum of exp(s - m)

// ---------------- projection GEMM: C[m,e] = sum_k X[m,k] * W[e,k] ----------------
// X: [4096,1024] row-major, W: [1024,1024] row-major ([out,in]).
// Writes to g_q/g_k/g_v in [b,h,s,d] layout. 128x128 tile, BK=16, 256 thr, 8x8/thr.
__global__ void __launch_bounds__(256) proj_kernel(const float* __restrict__ X,
                                                   const float* __restrict__ W,
                                                   int which)
{
    float* out = (which == 0) ? g_q : (which == 1) ? g_k : g_v;
    __shared__ float As[16][132];
    __shared__ float Bs[16][132];
    const int tid = threadIdx.x;
    const int tx = tid & 15, ty = tid >> 4;
    const int m0 = blockIdx.y * 128, n0 = blockIdx.x * 128;
    const int lr = tid >> 2;          // 0..63 (two passes: +0, +64)
    const int lc = (tid & 3) << 2;    // 0,4,8,12

    float acc[8][8];
    #pragma unroll
    for (int i = 0; i < 8; i++)
        #pragma unroll
        for (int j = 0; j < 8; j++) acc[i][j] = 0.f;

    for (int k0 = 0; k0 < DM; k0 += 16) {
        #pragma unroll
        for (int i = 0; i < 2; i++) {
            int r = lr + 64*i;
            float4 va = *(const float4*)(X + (size_t)(m0 + r)*DM + k0 + lc);
            As[lc+0][r] = va.x; As[lc+1][r] = va.y;
            As[lc+2][r] = va.z; As[lc+3][r] = va.w;
            float4 vb = *(const float4*)(W + (size_t)(n0 + r)*DM + k0 + lc);
            Bs[lc+0][r] = vb.x; Bs[lc+1][r] = vb.y;
            Bs[lc+2][r] = vb.z; Bs[lc+3][r] = vb.w;
        }
        __syncthreads();
        #pragma unroll
        for (int k = 0; k < 16; k++) {
            float a[8], b[8];
            *(float4*)(a)     = *(const float4*)&As[k][ty*8];
            *(float4*)(a + 4) = *(const float4*)&As[k][ty*8 + 4];
            *(float4*)(b)     = *(const float4*)&Bs[k][tx*8];
            *(float4*)(b + 4) = *(const float4*)&Bs[k][tx*8 + 4];
            #pragma unroll
            for (int i = 0; i < 8; i++)
                #pragma unroll
                for (int j = 0; j < 8; j++)
                    acc[i][j] = fmaf(a[i], b[j], acc[i][j]);
        }
        __syncthreads();
    }
    // epilogue: scatter to [b,h,s,d]
    #pragma unroll
    for (int i = 0; i < 8; i++) {
        int m = m0 + ty*8 + i;
        int b = m >> 11, s = m & (SEQ - 1);
        #pragma unroll
        for (int j = 0; j < 8; j += 4) {
            int e = n0 + tx*8 + j;
            int h = e >> 6, d = e & 63;
            float4 v = make_float4(acc[i][j], acc[i][j+1], acc[i][j+2], acc[i][j+3]);
            *(float4*)(out + (((size_t)(b*NH + h)*SEQ + s)*DQ + d)) = v;
        }
    }
}

// ---------------- fc GEMM: y[m,n] = sum_e O[m,e] * Wfc[n,e] ----------------
// O gathered from g_o's [b,h,s,d] layout; writes g_y [4096,1024] row-major.
__global__ void __launch_bounds__(256) fc_kernel(const float* __restrict__ Wfc)
{
    __shared__ float As[16][132];
    __shared__ float Bs[16][132];
    const int tid = threadIdx.x;
    const int tx = tid & 15, ty = tid >> 4;
    const int m0 = blockIdx.y * 128, n0 = blockIdx.x * 128;
    const int lr = tid >> 2;
    const int lc = (tid & 3) << 2;

    float acc[8][8];
    #pragma unroll
    for (int i = 0; i < 8; i++)
        #pragma unroll
        for (int j = 0; j < 8; j++) acc[i][j] = 0.f;

    for (int k0 = 0; k0 < DM; k0 += 16) {
        int e = k0 + lc;
        int h = e >> 6, d = e & 63;
        #pragma unroll
        for (int i = 0; i < 2; i++) {
            int r = lr + 64*i;
            int m = m0 + r;
            int b = m >> 11, s = m & (SEQ - 1);
            float4 va = *(const float4*)(g_o + ((size_t)(b*NH + h)*SEQ + s)*DQ + d);
            As[lc+0][r] = va.x; As[lc+1][r] = va.y;
            As[lc+2][r] = va.z; As[lc+3][r] = va.w;
            float4 vb = *(const float4*)(Wfc + (size_t)(n0 + r)*DM + k0 + lc);
            Bs[lc+0][r] = vb.x; Bs[lc+1][r] = vb.y;
            Bs[lc+2][r] = vb.z; Bs[lc+3][r] = vb.w;
        }
        __syncthreads();
        #pragma unroll
        for (int k = 0; k < 16; k++) {
            float a[8], b[8];
            *(float4*)(a)     = *(const float4*)&As[k][ty*8];
            *(float4*)(a + 4) = *(const float4*)&As[k][ty*8 + 4];
            *(float4*)(b)     = *(const float4*)&Bs[k][tx*8];
            *(float4*)(b + 4) = *(const float4*)&Bs[k][tx*8 + 4];
            #pragma unroll
            for (int i = 0; i < 8; i++)
                #pragma unroll
                for (int j = 0; j < 8; j++)
                    acc[i][j] = fmaf(a[i], b[j], acc[i][j]);
        }
        __syncthreads();
    }
    #pragma unroll
    for (int i = 0; i < 8; i++) {
        int m = m0 + ty*8 + i;
        #pragma unroll
        for (int j = 0; j < 8; j += 4) {
            float4 v = make_float4(acc[i][j], acc[i][j+1], acc[i][j+2], acc[i][j+3]);
            *(float4*)(g_y + (size_t)m*DM + n0 + tx*8 + j) = v;
        }
    }
}

// ---------------- scores: S = Q K^T, raw scores -> a-region, online (m,l) ----------
// grid (SEQ/64, BHN). CTA: 64 q-rows x all 2048 kv. 256 thr, 4x4/thr on 64x64 tiles.
__global__ void __launch_bounds__(256) scores_kernel(float* __restrict__ a_out)
{
    const int bh = blockIdx.y;
    const int q0 = blockIdx.x * 64;
    const float* Qp = g_q + (size_t)bh*SEQ*DQ;
    const float* Kp = g_k + (size_t)bh*SEQ*DQ;
    float* Sp = a_out + (size_t)bh*SEQ*SEQ;

    __shared__ float Qs[64][68];   // [k][q]
    __shared__ float Ks[64][68];   // [k][kv]
    const int tid = threadIdx.x;
    const int tx = tid & 15, ty = tid >> 4;
    const int lr = tid >> 4;          // 0..15
    const int lc = (tid & 15) << 2;   // 0..60

    #pragma unroll
    for (int i = 0; i < 4; i++) {
        int r = lr + 16*i;
        float4 v = *(const float4*)(Qp + (size_t)(q0 + r)*DQ + lc);
        Qs[lc+0][r] = v.x; Qs[lc+1][r] = v.y; Qs[lc+2][r] = v.z; Qs[lc+3][r] = v.w;
    }

    float run_m[4], run_l[4];
    #pragma unroll
    for (int i = 0; i < 4; i++) { run_m[i] = NEG_INF; run_l[i] = 0.f; }

    for (int kv0 = 0; kv0 < SEQ; kv0 += 64) {
        #pragma unroll
        for (int i = 0; i < 4; i++) {
            int r = lr + 16*i;
            float4 v = *(const float4*)(Kp + (size_t)(kv0 + r)*DQ + lc);
            Ks[lc+0][r] = v.x; Ks[lc+1][r] = v.y; Ks[lc+2][r] = v.z; Ks[lc+3][r] = v.w;
        }
        __syncthreads();

        float s[4][4];
        #pragma unroll
        for (int i = 0; i < 4; i++)
            #pragma unroll
            for (int j = 0; j < 4; j++) s[i][j] = 0.f;

        #pragma unroll 16
        for (int k = 0; k < 64; k++) {
            float a[4], b[4];
            *(float4*)a = *(const float4*)&Qs[k][ty*4];
            *(float4*)b = *(const float4*)&Ks[k][tx*4];
            #pragma unroll
            for (int i = 0; i < 4; i++)
                #pragma unroll
                for (int j = 0; j < 4; j++)
                    s[i][j] = fmaf(a[i], b[j], s[i][j]);
        }

        // exact online max/sumexp per row (butterfly over the 16 tx lanes)
        #pragma unroll
        for (int i = 0; i < 4; i++) {
            float tmax = fmaxf(fmaxf(s[i][0], s[i][1]), fmaxf(s[i][2], s[i][3]));
            #pragma unroll
            for (int o = 8; o; o >>= 1)
                tmax = fmaxf(tmax, __shfl_xor_sync(0xffffffffu, tmax, o));
            float nm = fmaxf(run_m[i], tmax);
            float tsum = __expf(s[i][0] - nm) + __expf(s[i][1] - nm)
                       + __expf(s[i][2] - nm) + __expf(s[i][3] - nm);
            #pragma unroll
            for (int o = 8; o; o >>= 1)
                tsum += __shfl_xor_sync(0xffffffffu, tsum, o);
            run_l[i] = run_l[i] * __expf(run_m[i] - nm) + tsum;
            run_m[i] = nm;
        }

        // store raw scores
        #pragma unroll
        for (int i = 0; i < 4; i++) {
            float4 v = make_float4(s[i][0], s[i][1], s[i][2], s[i][3]);
            *(float4*)(Sp + (size_t)(q0 + ty*4 + i)*SEQ + kv0 + tx*4) = v;
        }
        __syncthreads();
    }

    if (tx == 0) {
        #pragma unroll
        for (int i = 0; i < 4; i++) {
            g_m[(size_t)bh*SEQ + q0 + ty*4 + i] = run_m[i];
            g_l[(size_t)bh*SEQ + q0 + ty*4 + i] = run_l[i];
        }
    }
}

// ---------------- AV: normalize probs in-place + O = P V ----------------
// grid (SEQ/64, BHN). CTA: 64 q-rows x 64 d-cols, loop kv tiles of 64.
__global__ void __launch_bounds__(256) av_kernel(float* __restrict__ a_out)
{
    const int bh = blockIdx.y;
    const int q0 = blockIdx.x * 64;
    const float* Vp = g_v + (size_t)bh*SEQ*DQ;
    float* Sp = a_out + (size_t)bh*SEQ*SEQ;

    __shared__ float Ps[64][68];   // [kv][q]
    __shared__ float Vs[64][68];   // [kv][d]
    __shared__ float sm_m[64], sm_il[64];
    const int tid = threadIdx.x;
    const int tx = tid & 15, ty = tid >> 4;
    const int lr = tid >> 4;
    const int lc = (tid & 15) << 2;

    if (tid < 64) {
        sm_m[tid]  = g_m[(size_t)bh*SEQ + q0 + tid];
        sm_il[tid] = 1.0f / g_l[(size_t)bh*SEQ + q0 + tid];
    }
    __syncthreads();

    float acc[4][4];
    #pragma unroll
    for (int i = 0; i < 4; i++)
        #pragma unroll
        for (int j = 0; j < 4; j++) acc[i][j] = 0.f;

    for (int kv0 = 0; kv0 < SEQ; kv0 += 64) {
        #pragma unroll
        for (int i = 0; i < 4; i++) {
            int r = lr + 16*i;
            float* sp = Sp + (size_t)(q0 + r)*SEQ + kv0 + lc;
            float4 v = *(const float4*)sp;
            float m = sm_m[r], il = sm_il[r];
            float4 p;
            p.x = __expf(v.x - m) * il;
            p.y = __expf(v.y - m) * il;
            p.z = __expf(v.z - m) * il;
            p.w = __expf(v.w - m) * il;
            *(float4*)sp = p;                       // final attention probs
            Ps[lc+0][r] = p.x; Ps[lc+1][r] = p.y;
            Ps[lc+2][r] = p.z; Ps[lc+3][r] = p.w;
            float4 w = *(const float4*)(Vp + (size_t)(kv0 + r)*DQ + lc);
            *(float4*)&Vs[r][lc] = w;
        }
        __syncthreads();

        #pragma unroll 16
        for (int k = 0; k < 64; k++) {
            float a[4], b[4];
            *(float4*)a = *(const float4*)&Ps[k][ty*4];
            *(float4*)b = *(const float4*)&Vs[k][tx*4];
            #pragma unroll
            for (int i = 0; i < 4; i++)
                #pragma unroll
                for (int j = 0; j < 4; j++)
                    acc[i][j] = fmaf(a[i], b[j], acc[i][j]);
        }
        __syncthreads();
    }

    #pragma unroll
    for (int i = 0; i < 4; i++) {
        float4 v = make_float4(acc[i][0], acc[i][1], acc[i][2], acc[i][3]);
        *(float4*)(g_o + ((size_t)bh*SEQ + q0 + ty*4 + i)*DQ + tx*4) = v;
    }
}

// ---------------- residual + LayerNorm ----------------
// grid 4096 rows, 256 thr; each thread owns 4 contiguous floats.
__global__ void __launch_bounds__(256) ln_kernel(const float* __restrict__ xq,
                                                 float* __restrict__ out)
{
    const int r = blockIdx.x;
    const int t = threadIdx.x;
    float4 a = ((const float4*)(g_y + (size_t)r*DM))[t];
    float4 b = ((const float4*)(xq  + (size_t)r*DM))[t];
    float z0 = a.x + b.x, z1 = a.y + b.y, z2 = a.z + b.z, z3 = a.w + b.w;
    float s = z0 + z1 + z2 + z3;
    float q = z0*z0 + z1*z1 + z2*z2 + z3*z3;

    __shared__ float red[2][8];
    #pragma unroll
    for (int o = 16; o; o >>= 1) {
        s += __shfl_xor_sync(0xffffffffu, s, o);
        q += __shfl_xor_sync(0xffffffffu, q, o);
    }
    int w = t >> 5, l = t & 31;
    if (l == 0) { red[0][w] = s; red[1][w] = q; }
    __syncthreads();
    float S = 0.f, Q = 0.f;
    #pragma unroll
    for (int i = 0; i < 8; i++) { S += red[0][i]; Q += red[1][i]; }
    float mu  = S * (1.0f / DM);
    float var = Q * (1.0f / DM) - mu * mu;
    float inv = rsqrtf(var + 1e-5f);
    float4 o;
    o.x = (z0 - mu) * inv; o.y = (z1 - mu) * inv;
    o.z = (z2 - mu) * inv; o.w = (z3 - mu) * inv;
    ((float4*)(out + (size_t)r*DM))[t] = o;
}

// ---------------- launch ----------------
extern "C" void kernel_launch(void* const* d_in, const int* in_sizes, int n_in,
                              void* d_out, int out_size)
{
    (void)in_sizes; (void)n_in; (void)out_size;
    const float* xq  = (const float*)d_in[0];
    const float* xk  = (const float*)d_in[1];
    const float* xv  = (const float*)d_in[2];
    const float* WQ  = (const float*)d_in[3];
    const float* WK  = (const float*)d_in[4];
    const float* WV  = (const float*)d_in[5];
    const float* Wfc = (const float*)d_in[6];

    float* a_out = (float*)d_out;                                  // [2,16,2048,2048]
    float* o_out = (float*)d_out + (size_t)BHN*SEQ*SEQ;            // [2,2048,1024]

    dim3 pg(DM/128, (BS*SEQ)/128);   // (8, 32)
    dim3 ag(SEQ/64, BHN);            // (32, 32)

    proj_kernel<<<pg, 256>>>(xq, WQ, 0);
    proj_kernel<<<pg, 256>>>(xk, WK, 1);
    proj_kernel<<<pg, 256>>>(xv, WV, 2);
    scores_kernel<<<ag, 256>>>(a_out);
    av_kernel<<<ag, 256>>>(a_out);
    fc_kernel<<<pg, 256>>>(Wfc);
    ln_kernel<<<BS*SEQ, 256>>>(xq, o_out);
}

// round 16
// speedup vs baseline: 1.6502x; 1.6466x over previous
#include <cuda_runtime.h>
#include <cuda_bf16.h>
#include <mma.h>
#include <math.h>
#include <stdint.h>

using namespace nvcuda;

#define BS   2
#define SEQ  2048
#define DM   1024
#define NH   16
#define DQ   64
#define BHN  (BS*NH)
#define NEG_INF (-1e30f)

typedef wmma::fragment<wmma::matrix_a, 16,16,16, __nv_bfloat16, wmma::row_major> FragA;
typedef wmma::fragment<wmma::matrix_b, 16,16,16, __nv_bfloat16, wmma::col_major> FragBc;
typedef wmma::fragment<wmma::matrix_b, 16,16,16, __nv_bfloat16, wmma::row_major> FragBr;
typedef wmma::fragment<wmma::accumulator, 16,16,16, float> FragC;

// ---------------- scratch (device globals) ----------------
__device__ __nv_bfloat16 g_xqh[(size_t)BS*SEQ*DM], g_xql[(size_t)BS*SEQ*DM];
__device__ __nv_bfloat16 g_xkh[(size_t)BS*SEQ*DM], g_xkl[(size_t)BS*SEQ*DM];
__device__ __nv_bfloat16 g_xvh[(size_t)BS*SEQ*DM], g_xvl[(size_t)BS*SEQ*DM];
__device__ __nv_bfloat16 g_wqh[(size_t)DM*DM], g_wql[(size_t)DM*DM];
__device__ __nv_bfloat16 g_wkh[(size_t)DM*DM], g_wkl[(size_t)DM*DM];
__device__ __nv_bfloat16 g_wvh[(size_t)DM*DM], g_wvl[(size_t)DM*DM];
__device__ __nv_bfloat16 g_wfh[(size_t)DM*DM], g_wfl[(size_t)DM*DM];
__device__ __nv_bfloat16 g_qh[(size_t)BHN*SEQ*DQ], g_ql[(size_t)BHN*SEQ*DQ];
__device__ __nv_bfloat16 g_kh[(size_t)BHN*SEQ*DQ], g_kl[(size_t)BHN*SEQ*DQ];
__device__ __nv_bfloat16 g_vh[(size_t)BHN*SEQ*DQ], g_vl[(size_t)BHN*SEQ*DQ];
__device__ __nv_bfloat16 g_oh[(size_t)BHN*SEQ*DQ], g_ol[(size_t)BHN*SEQ*DQ];
__device__ float g_y[(size_t)BS*SEQ*DM];
__device__ float g_m[(size_t)BHN*SEQ];
__device__ float g_l[(size_t)BHN*SEQ];

__device__ __forceinline__ void split_store(__nv_bfloat16* hi, __nv_bfloat16* lo,
                                            size_t idx, float v0, float v1)
{
    __nv_bfloat16 h0 = __float2bfloat16(v0), h1 = __float2bfloat16(v1);
    *(__nv_bfloat162*)(hi + idx) = __halves2bfloat162(h0, h1);
    *(__nv_bfloat162*)(lo + idx) = __halves2bfloat162(
        __float2bfloat16(v0 - __bfloat162float(h0)),
        __float2bfloat16(v1 - __bfloat162float(h1)));
}

// ---------------- split fp32 -> bf16 hi/lo ----------------
__global__ void __launch_bounds__(256) split_kernel(const float4* __restrict__ src,
                                                    int which, int n4)
{
    __nv_bfloat16 *hi, *lo;
    switch (which) {
        case 0: hi = g_xqh; lo = g_xql; break;
        case 1: hi = g_xkh; lo = g_xkl; break;
        case 2: hi = g_xvh; lo = g_xvl; break;
        case 3: hi = g_wqh; lo = g_wql; break;
        case 4: hi = g_wkh; lo = g_wkl; break;
        case 5: hi = g_wvh; lo = g_wvl; break;
        default: hi = g_wfh; lo = g_wfl; break;
    }
    int i = blockIdx.x*256 + threadIdx.x;
    if (i >= n4) return;
    float4 v = src[i];
    split_store(hi, lo, (size_t)i*4,     v.x, v.y);
    split_store(hi, lo, (size_t)i*4 + 2, v.z, v.w);
}

// ---------------- GEMM (wmma, bf16x3): C[m,n] = sum_k A[m,k]*B[n,k] ----------------
// M=4096, N=1024, K=1024. which 0/1/2 = Q/K/V proj (out hi/lo in [b,h,s,d]); 3 = fc (g_y).
__global__ void __launch_bounds__(256) gemm_wmma(int which)
{
    __shared__ __align__(16) char sm[40960];
    __nv_bfloat16* Ah_s = (__nv_bfloat16*)sm;            // 128 x 40
    __nv_bfloat16* Al_s = Ah_s + 128*40;
    __nv_bfloat16* Bh_s = Al_s + 128*40;
    __nv_bfloat16* Bl_s = Bh_s + 128*40;
    float* Cst = (float*)sm;                              // overlay after k-loop: 128 x 68

    const int tid = threadIdx.x, wid = tid>>5;
    const int wm = wid & 3, wn = wid >> 2;
    const int m0 = blockIdx.y*128, n0 = blockIdx.x*128;

    const uint4 *Ah, *Al, *Bh, *Bl;
    if      (which==0){ Ah=(const uint4*)g_xqh; Al=(const uint4*)g_xql; Bh=(const uint4*)g_wqh; Bl=(const uint4*)g_wql; }
    else if (which==1){ Ah=(const uint4*)g_xkh; Al=(const uint4*)g_xkl; Bh=(const uint4*)g_wkh; Bl=(const uint4*)g_wkl; }
    else if (which==2){ Ah=(const uint4*)g_xvh; Al=(const uint4*)g_xvl; Bh=(const uint4*)g_wvh; Bl=(const uint4*)g_wvl; }
    else              { Ah=(const uint4*)g_oh;  Al=(const uint4*)g_ol;  Bh=(const uint4*)g_wfh; Bl=(const uint4*)g_wfl; }

    FragC acc[2][4];
    #pragma unroll
    for (int i = 0; i < 2; i++)
        #pragma unroll
        for (int j = 0; j < 4; j++) wmma::fill_fragment(acc[i][j], 0.0f);

    for (int k0 = 0; k0 < DM; k0 += 32) {
        for (int c = tid; c < 512; c += 256) {
            int r = c>>2, q = c&3;
            size_t aidx;
            if (which == 3) {
                int m = m0 + r, b = m>>11, s = m&(SEQ-1), h = k0>>6;
                aidx = ((size_t)(b*NH + h)*SEQ + s)*8 + ((k0&63)>>3) + q;
            } else {
                aidx = (size_t)(m0 + r)*128 + (k0>>3) + q;
            }
            *(uint4*)&Ah_s[r*40 + q*8] = Ah[aidx];
            *(uint4*)&Al_s[r*40 + q*8] = Al[aidx];
            size_t bidx = (size_t)(n0 + r)*128 + (k0>>3) + q;
            *(uint4*)&Bh_s[r*40 + q*8] = Bh[bidx];
            *(uint4*)&Bl_s[r*40 + q*8] = Bl[bidx];
        }
        __syncthreads();
        #pragma unroll
        for (int ks = 0; ks < 32; ks += 16) {
            FragA ah[2], al[2];
            #pragma unroll
            for (int i = 0; i < 2; i++) {
                wmma::load_matrix_sync(ah[i], &Ah_s[(wm*32 + i*16)*40 + ks], 40);
                wmma::load_matrix_sync(al[i], &Al_s[(wm*32 + i*16)*40 + ks], 40);
            }
            #pragma unroll
            for (int j = 0; j < 4; j++) {
                FragBc bh, bl;
                wmma::load_matrix_sync(bh, &Bh_s[(wn*64 + j*16)*40 + ks], 40);
                wmma::load_matrix_sync(bl, &Bl_s[(wn*64 + j*16)*40 + ks], 40);
                #pragma unroll
                for (int i = 0; i < 2; i++) {
                    wmma::mma_sync(acc[i][j], ah[i], bh, acc[i][j]);
                    wmma::mma_sync(acc[i][j], ah[i], bl, acc[i][j]);
                    wmma::mma_sync(acc[i][j], al[i], bh, acc[i][j]);
                }
            }
        }
        __syncthreads();
    }

    if (which == 3) {
        #pragma unroll
        for (int i = 0; i < 2; i++)
            #pragma unroll
            for (int j = 0; j < 4; j++)
                wmma::store_matrix_sync(&g_y[(size_t)(m0 + wm*32 + i*16)*DM + n0 + wn*64 + j*16],
                                        acc[i][j], DM, wmma::mem_row_major);
    } else {
        __nv_bfloat16 *oh, *ol;
        if      (which == 0){ oh = g_qh; ol = g_ql; }
        else if (which == 1){ oh = g_kh; ol = g_kl; }
        else               { oh = g_vh; ol = g_vl; }
        for (int half = 0; half < 2; half++) {
            if (wn == half) {
                #pragma unroll
                for (int i = 0; i < 2; i++)
                    #pragma unroll
                    for (int j = 0; j < 4; j++)
                        wmma::store_matrix_sync(&Cst[(wm*32 + i*16)*68 + j*16],
                                                acc[i][j], 68, wmma::mem_row_major);
            }
            __syncthreads();
            int r = tid>>1, cbase = (tid&1)*32;
            int m = m0 + r, b = m>>11, s = m&(SEQ-1);
            int h = (n0 + half*64) >> 6;
            size_t base = ((size_t)(b*NH + h)*SEQ + s)*DQ + cbase;
            #pragma unroll
            for (int c = 0; c < 32; c += 2)
                split_store(oh, ol, base + c, Cst[r*68 + cbase + c], Cst[r*68 + cbase + c + 1]);
            __syncthreads();
        }
    }
}

// ---------------- scores (wmma): raw S -> a-region + online (m,l) ----------------
// grid (16, 32). CTA: 128 q-rows x 2048 kv in 32 tiles of 64.
#define SC_QH   0                      // 128*72 bf16 = 18432 B
#define SC_QL   18432
#define SC_KH   36864                  // 64*72 bf16 = 9216 B
#define SC_KL   46080
#define SC_SST  55296                  // 128*68 f32 = 34816 B
#define SC_NM   90112                  // 128 f32
#define SC_PMAX 90624                  // 256 f32
#define SC_PSUM 91648                  // 256 f32
#define SC_BYTES 92672

__global__ void __launch_bounds__(256) scores_wmma(float* __restrict__ a_out)
{
    extern __shared__ __align__(16) char sm[];
    __nv_bfloat16* Qh_s = (__nv_bfloat16*)(sm + SC_QH);
    __nv_bfloat16* Ql_s = (__nv_bfloat16*)(sm + SC_QL);
    __nv_bfloat16* Kh_s = (__nv_bfloat16*)(sm + SC_KH);
    __nv_bfloat16* Kl_s = (__nv_bfloat16*)(sm + SC_KL);
    float* Sst  = (float*)(sm + SC_SST);
    float* nm_s = (float*)(sm + SC_NM);
    float* pmax = (float*)(sm + SC_PMAX);
    float* psum = (float*)(sm + SC_PSUM);

    const int tid = threadIdx.x, wid = tid>>5;
    const int wm = wid & 3, wn = wid >> 2;
    const int bh = blockIdx.y, q0 = blockIdx.x*128;
    float* Sp = a_out + (size_t)bh*SEQ*SEQ;
    const uint4* qh = (const uint4*)g_qh + (size_t)bh*SEQ*8;
    const uint4* ql = (const uint4*)g_ql + (size_t)bh*SEQ*8;
    const uint4* kh = (const uint4*)g_kh + (size_t)bh*SEQ*8;
    const uint4* kl = (const uint4*)g_kl + (size_t)bh*SEQ*8;

    for (int c = tid; c < 1024; c += 256) {
        int r = c>>3, q = c&7;
        *(uint4*)&Qh_s[r*72 + q*8] = qh[(size_t)(q0 + r)*8 + q];
        *(uint4*)&Ql_s[r*72 + q*8] = ql[(size_t)(q0 + r)*8 + q];
    }

    const int rr = tid & 127, rhalf = tid >> 7;
    float run_m = NEG_INF, run_l = 0.f;

    for (int t = 0; t < 32; t++) {
        const int kv0 = t*64;
        for (int c = tid; c < 512; c += 256) {
            int r = c>>3, q = c&7;
            *(uint4*)&Kh_s[r*72 + q*8] = kh[(size_t)(kv0 + r)*8 + q];
            *(uint4*)&Kl_s[r*72 + q*8] = kl[(size_t)(kv0 + r)*8 + q];
        }
        __syncthreads();

        FragC acc[2][2];
        #pragma unroll
        for (int i = 0; i < 2; i++)
            #pragma unroll
            for (int j = 0; j < 2; j++) wmma::fill_fragment(acc[i][j], 0.0f);
        #pragma unroll
        for (int ks = 0; ks < 64; ks += 16) {
            FragA ah[2], al[2];
            #pragma unroll
            for (int i = 0; i < 2; i++) {
                wmma::load_matrix_sync(ah[i], &Qh_s[(wm*32 + i*16)*72 + ks], 72);
                wmma::load_matrix_sync(al[i], &Ql_s[(wm*32 + i*16)*72 + ks], 72);
            }
            #pragma unroll
            for (int j = 0; j < 2; j++) {
                FragBc bh2, bl2;
                wmma::load_matrix_sync(bh2, &Kh_s[(wn*32 + j*16)*72 + ks], 72);
                wmma::load_matrix_sync(bl2, &Kl_s[(wn*32 + j*16)*72 + ks], 72);
                #pragma unroll
                for (int i = 0; i < 2; i++) {
                    wmma::mma_sync(acc[i][j], ah[i], bh2, acc[i][j]);
                    wmma::mma_sync(acc[i][j], ah[i], bl2, acc[i][j]);
                    wmma::mma_sync(acc[i][j], al[i], bh2, acc[i][j]);
                }
            }
        }
        #pragma unroll
        for (int i = 0; i < 2; i++)
            #pragma unroll
            for (int j = 0; j < 2; j++)
                wmma::store_matrix_sync(&Sst[(wm*32 + i*16)*68 + wn*32 + j*16],
                                        acc[i][j], 68, wmma::mem_row_major);
        __syncthreads();

        // coalesced raw-S write to global
        for (int idx = tid; idx < 2048; idx += 256) {
            int r = idx>>4, c4 = (idx&15)*4;
            *(float4*)(Sp + (size_t)(q0 + r)*SEQ + kv0 + c4) = *(float4*)&Sst[r*68 + c4];
        }
        // row max (half-rows)
        float hm = NEG_INF;
        #pragma unroll
        for (int i = 0; i < 8; i++) {
            float4 v = *(float4*)&Sst[rr*68 + rhalf*32 + i*4];
            hm = fmaxf(hm, fmaxf(fmaxf(v.x, v.y), fmaxf(v.z, v.w)));
        }
        pmax[rr*2 + rhalf] = hm;
        __syncthreads();
        if (tid < 128)
            nm_s[tid] = fmaxf(run_m, fmaxf(pmax[tid*2], pmax[tid*2 + 1]));
        __syncthreads();
        const float nm = nm_s[rr];
        float es = 0.f;
        #pragma unroll
        for (int i = 0; i < 8; i++) {
            float4 v = *(float4*)&Sst[rr*68 + rhalf*32 + i*4];
            es += __expf(v.x - nm) + __expf(v.y - nm) + __expf(v.z - nm) + __expf(v.w - nm);
        }
        psum[rr*2 + rhalf] = es;
        __syncthreads();
        if (tid < 128) {
            const float nm2 = nm_s[tid];
            run_l = run_l * __expf(run_m - nm2) + psum[tid*2] + psum[tid*2 + 1];
            run_m = nm2;
        }
    }
    if (tid < 128) {
        g_m[(size_t)bh*SEQ + q0 + tid] = run_m;
        g_l[(size_t)bh*SEQ + q0 + tid] = run_l;
    }
}

// ---------------- AV (wmma): normalize probs in-place, O = P V, out hi/lo -----------
#define AV_PH   0                      // 128*72 bf16 = 18432 B
#define AV_PL   18432
#define AV_VH   36864                  // 64*72 bf16 = 9216 B
#define AV_VL   46080
#define AV_M    55296                  // 128 f32
#define AV_IL   55808                  // 128 f32
#define AV_BYTES 56320
// O staging overlays AV_PH (128*68*4 = 34816 <= 36864)

__global__ void __launch_bounds__(256) av_wmma(float* __restrict__ a_out)
{
    extern __shared__ __align__(16) char sm[];
    __nv_bfloat16* Ph_s = (__nv_bfloat16*)(sm + AV_PH);
    __nv_bfloat16* Pl_s = (__nv_bfloat16*)(sm + AV_PL);
    __nv_bfloat16* Vh_s = (__nv_bfloat16*)(sm + AV_VH);
    __nv_bfloat16* Vl_s = (__nv_bfloat16*)(sm + AV_VL);
    float* sm_m  = (float*)(sm + AV_M);
    float* sm_il = (float*)(sm + AV_IL);
    float* Ost   = (float*)(sm + AV_PH);   // overlay after kv loop

    const int tid = threadIdx.x, wid = tid>>5;
    const int wm = wid & 3, wn = wid >> 2;
    const int bh = blockIdx.y, q0 = blockIdx.x*128;
    float* Sp = a_out + (size_t)bh*SEQ*SEQ;
    const uint4* vh = (const uint4*)g_vh + (size_t)bh*SEQ*8;
    const uint4* vl = (const uint4*)g_vl + (size_t)bh*SEQ*8;

    if (tid < 128) {
        sm_m[tid]  = g_m[(size_t)bh*SEQ + q0 + tid];
        sm_il[tid] = 1.0f / g_l[(size_t)bh*SEQ + q0 + tid];
    }
    __syncthreads();

    FragC acc[2][2];
    #pragma unroll
    for (int i = 0; i < 2; i++)
        #pragma unroll
        for (int j = 0; j < 2; j++) wmma::fill_fragment(acc[i][j], 0.0f);

    for (int t = 0; t < 32; t++) {
        const int kv0 = t*64;
        // load raw S, normalize -> prob write-back + split into Ph/Pl smem
        #pragma unroll
        for (int p = 0; p < 4; p++) {
            int r  = p*32 + (tid>>3);
            int c0 = (tid&7)*4;
            float m = sm_m[r], il = sm_il[r];
            #pragma unroll
            for (int h2 = 0; h2 < 2; h2++) {
                int c = c0 + h2*32;
                float* sp = Sp + (size_t)(q0 + r)*SEQ + kv0 + c;
                float4 v = *(const float4*)sp;
                float4 pr;
                pr.x = __expf(v.x - m)*il; pr.y = __expf(v.y - m)*il;
                pr.z = __expf(v.z - m)*il; pr.w = __expf(v.w - m)*il;
                *(float4*)sp = pr;
                split_store(Ph_s, Pl_s, (size_t)r*72 + c,     pr.x, pr.y);
                split_store(Ph_s, Pl_s, (size_t)r*72 + c + 2, pr.z, pr.w);
            }
        }
        for (int c = tid; c < 512; c += 256) {
            int r = c>>3, q = c&7;
            *(uint4*)&Vh_s[r*72 + q*8] = vh[(size_t)(kv0 + r)*8 + q];
            *(uint4*)&Vl_s[r*72 + q*8] = vl[(size_t)(kv0 + r)*8 + q];
        }
        __syncthreads();

        #pragma unroll
        for (int ks = 0; ks < 64; ks += 16) {
            FragA ah[2], al[2];
            #pragma unroll
            for (int i = 0; i < 2; i++) {
                wmma::load_matrix_sync(ah[i], &Ph_s[(wm*32 + i*16)*72 + ks], 72);
                wmma::load_matrix_sync(al[i], &Pl_s[(wm*32 + i*16)*72 + ks], 72);
            }
            #pragma unroll
            for (int j = 0; j < 2; j++) {
                FragBr bh2, bl2;
                wmma::load_matrix_sync(bh2, &Vh_s[ks*72 + wn*32 + j*16], 72);
                wmma::load_matrix_sync(bl2, &Vl_s[ks*72 + wn*32 + j*16], 72);
                #pragma unroll
                for (int i = 0; i < 2; i++) {
                    wmma::mma_sync(acc[i][j], ah[i], bh2, acc[i][j]);
                    wmma::mma_sync(acc[i][j], ah[i], bl2, acc[i][j]);
                    wmma::mma_sync(acc[i][j], al[i], bh2, acc[i][j]);
                }
            }
        }
        __syncthreads();
    }

    // epilogue: stage O, convert to hi/lo bf16 in [b,h,s,d]
    #pragma unroll
    for (int i = 0; i < 2; i++)
        #pragma unroll
        for (int j = 0; j < 2; j++)
            wmma::store_matrix_sync(&Ost[(wm*32 + i*16)*68 + wn*32 + j*16],
                                    acc[i][j], 68, wmma::mem_row_major);
    __syncthreads();
    {
        int r = tid>>1, cbase = (tid&1)*32;
        size_t base = ((size_t)bh*SEQ + q0 + r)*DQ + cbase;
        #pragma unroll
        for (int c = 0; c < 32; c += 2)
            split_store(g_oh, g_ol, base + c, Ost[r*68 + cbase + c], Ost[r*68 + cbase + c + 1]);
    }
}

// ---------------- residual + LayerNorm ----------------
__global__ void __launch_bounds__(256) ln_kernel(const float* __restrict__ xq,
                                                 float* __restrict__ out)
{
    const int r = blockIdx.x;
    const int t = threadIdx.x;
    float4 a = ((const float4*)(g_y + (size_t)r*DM))[t];
    float4 b = ((const float4*)(xq  + (size_t)r*DM))[t];
    float z0 = a.x + b.x, z1 = a.y + b.y, z2 = a.z + b.z, z3 = a.w + b.w;
    float s = z0 + z1 + z2 + z3;
    float q = z0*z0 + z1*z1 + z2*z2 + z3*z3;

    __shared__ float red[2][8];
    #pragma unroll
    for (int o = 16; o; o >>= 1) {
        s += __shfl_xor_sync(0xffffffffu, s, o);
        q += __shfl_xor_sync(0xffffffffu, q, o);
    }
    int w = t >> 5, l = t & 31;
    if (l == 0) { red[0][w] = s; red[1][w] = q; }
    __syncthreads();
    float S = 0.f, Q = 0.f;
    #pragma unroll
    for (int i = 0; i < 8; i++) { S += red[0][i]; Q += red[1][i]; }
    float mu  = S * (1.0f / DM);
    float var = Q * (1.0f / DM) - mu * mu;
    float inv = rsqrtf(var + 1e-5f);
    float4 o;
    o.x = (z0 - mu) * inv; o.y = (z1 - mu) * inv;
    o.z = (z2 - mu) * inv; o.w = (z3 - mu) * inv;
    ((float4*)(out + (size_t)r*DM))[t] = o;
}

// ---------------- launch ----------------
extern "C" void kernel_launch(void* const* d_in, const int* in_sizes, int n_in,
                              void* d_out, int out_size)
{
    (void)in_sizes; (void)n_in; (void)out_size;
    const float* xq  = (const float*)d_in[0];
    const float* xk  = (const float*)d_in[1];
    const float* xv  = (const float*)d_in[2];
    const float* WQ  = (const float*)d_in[3];
    const float* WK  = (const float*)d_in[4];
    const float* WV  = (const float*)d_in[5];
    const float* Wfc = (const float*)d_in[6];

    float* a_out = (float*)d_out;                         // [2,16,2048,2048]
    float* o_out = (float*)d_out + (size_t)BHN*SEQ*SEQ;   // [2,2048,1024]

    cudaFuncSetAttribute(scores_wmma, cudaFuncAttributeMaxDynamicSharedMemorySize, SC_BYTES);
    cudaFuncSetAttribute(av_wmma,     cudaFuncAttributeMaxDynamicSharedMemorySize, AV_BYTES);

    const int nx4 = BS*SEQ*DM/4;   // 1048576
    const int nw4 = DM*DM/4;       // 262144
    split_kernel<<<nx4/256, 256>>>((const float4*)xq,  0, nx4);
    split_kernel<<<nx4/256, 256>>>((const float4*)xk,  1, nx4);
    split_kernel<<<nx4/256, 256>>>((const float4*)xv,  2, nx4);
    split_kernel<<<nw4/256, 256>>>((const float4*)WQ,  3, nw4);
    split_kernel<<<nw4/256, 256>>>((const float4*)WK,  4, nw4);
    split_kernel<<<nw4/256, 256>>>((const float4*)WV,  5, nw4);
    split_kernel<<<nw4/256, 256>>>((const float4*)Wfc, 6, nw4);

    dim3 gg(DM/128, (BS*SEQ)/128);   // (8, 32)
    gemm_wmma<<<gg, 256>>>(0);
    gemm_wmma<<<gg, 256>>>(1);
    gemm_wmma<<<gg, 256>>>(2);

    scores_wmma<<<dim3(SEQ/128, BHN), 256, SC_BYTES>>>(a_out);
    av_wmma<<<dim3(SEQ/128, BHN), 256, AV_BYTES>>>(a_out);

    gemm_wmma<<<gg, 256>>>(3);
    ln_kernel<<<BS*SEQ, 256>>>(xq, o_out);
}

// round 17
// speedup vs baseline: 1.7357x; 1.0518x over previous
#include <cuda_runtime.h>
#include <cuda_bf16.h>
#include <mma.h>
#include <math.h>
#include <stdint.h>

using namespace nvcuda;

#define BS   2
#define SEQ  2048
#define DM   1024
#define NH   16
#define DQ   64
#define BHN  (BS*NH)
#define NEG_INF (-1e30f)

typedef wmma::fragment<wmma::matrix_a, 16,16,16, __nv_bfloat16, wmma::row_major> FragA;
typedef wmma::fragment<wmma::matrix_b, 16,16,16, __nv_bfloat16, wmma::col_major> FragBc;
typedef wmma::fragment<wmma::matrix_b, 16,16,16, __nv_bfloat16, wmma::row_major> FragBr;
typedef wmma::fragment<wmma::accumulator, 16,16,16, float> FragC;

// ---------------- scratch ----------------
__device__ __nv_bfloat16 g_xqh[(size_t)BS*SEQ*DM], g_xql[(size_t)BS*SEQ*DM];
__device__ __nv_bfloat16 g_xkh[(size_t)BS*SEQ*DM], g_xkl[(size_t)BS*SEQ*DM];
__device__ __nv_bfloat16 g_xvh[(size_t)BS*SEQ*DM], g_xvl[(size_t)BS*SEQ*DM];
__device__ __nv_bfloat16 g_wqh[(size_t)DM*DM], g_wql[(size_t)DM*DM];
__device__ __nv_bfloat16 g_wkh[(size_t)DM*DM], g_wkl[(size_t)DM*DM];
__device__ __nv_bfloat16 g_wvh[(size_t)DM*DM], g_wvl[(size_t)DM*DM];
__device__ __nv_bfloat16 g_wfh[(size_t)DM*DM], g_wfl[(size_t)DM*DM];
__device__ __nv_bfloat16 g_qh[(size_t)BHN*SEQ*DQ], g_ql[(size_t)BHN*SEQ*DQ];
__device__ __nv_bfloat16 g_kh[(size_t)BHN*SEQ*DQ], g_kl[(size_t)BHN*SEQ*DQ];
__device__ __nv_bfloat16 g_vh[(size_t)BHN*SEQ*DQ], g_vl[(size_t)BHN*SEQ*DQ];
__device__ __nv_bfloat16 g_oh[(size_t)BHN*SEQ*DQ], g_ol[(size_t)BHN*SEQ*DQ];
__device__ float g_y[(size_t)BS*SEQ*DM];
__device__ float g_m[(size_t)BHN*SEQ];
__device__ float g_l[(size_t)BHN*SEQ];

// ---------------- helpers ----------------
__device__ __forceinline__ void split_store(__nv_bfloat16* hi, __nv_bfloat16* lo,
                                            size_t idx, float v0, float v1)
{
    __nv_bfloat16 h0 = __float2bfloat16(v0), h1 = __float2bfloat16(v1);
    *(__nv_bfloat162*)(hi + idx) = __halves2bfloat162(h0, h1);
    *(__nv_bfloat162*)(lo + idx) = __halves2bfloat162(
        __float2bfloat16(v0 - __bfloat162float(h0)),
        __float2bfloat16(v1 - __bfloat162float(h1)));
}
__device__ __forceinline__ void cp16(void* dst_smem, const void* src){
    uint32_t d = (uint32_t)__cvta_generic_to_shared(dst_smem);
    asm volatile("cp.async.cg.shared.global [%0], [%1], 16;" :: "r"(d), "l"(src));
}
__device__ __forceinline__ void cp_commit(){ asm volatile("cp.async.commit_group;"); }
template<int N> __device__ __forceinline__ void cp_wait(){
    asm volatile("cp.async.wait_group %0;" :: "n"(N));
}

// ---------------- mega split: all 7 fp32 tensors -> bf16 hi/lo, one launch -----------
__global__ void __launch_bounds__(256) split_all(const float4* __restrict__ xq,
                                                 const float4* __restrict__ xk,
                                                 const float4* __restrict__ xv,
                                                 const float4* __restrict__ wq,
                                                 const float4* __restrict__ wk,
                                                 const float4* __restrict__ wv,
                                                 const float4* __restrict__ wf)
{
    int blk = blockIdx.x;
    const float4* src; __nv_bfloat16 *hi, *lo; int base;
    if      (blk <  4096){ src = xq; hi = g_xqh; lo = g_xql; base = blk; }
    else if (blk <  8192){ src = xk; hi = g_xkh; lo = g_xkl; base = blk - 4096; }
    else if (blk < 12288){ src = xv; hi = g_xvh; lo = g_xvl; base = blk - 8192; }
    else if (blk < 13312){ src = wq; hi = g_wqh; lo = g_wql; base = blk - 12288; }
    else if (blk < 14336){ src = wk; hi = g_wkh; lo = g_wkl; base = blk - 13312; }
    else if (blk < 15360){ src = wv; hi = g_wvh; lo = g_wvl; base = blk - 14336; }
    else                 { src = wf; hi = g_wfh; lo = g_wfl; base = blk - 15360; }
    int i = base*256 + threadIdx.x;
    float4 v = src[i];
    split_store(hi, lo, (size_t)i*4,     v.x, v.y);
    split_store(hi, lo, (size_t)i*4 + 2, v.z, v.w);
}

// ---------------- GEMM (wmma bf16x3, cp.async 2-stage): C[m,n]=sum_k A[m,k]B[n,k] ----
// M=4096, N=1024, K=1024. which 0/1/2 = Q/K/V proj; 3 = fc -> g_y.
#define G_STG 40960
#define G_BYTES (2*G_STG)

__global__ void __launch_bounds__(256) gemm_wmma(int which)
{
    extern __shared__ __align__(16) char sm[];
    const int tid = threadIdx.x, wid = tid>>5;
    const int wm = wid & 3, wn = wid >> 2;
    const int m0 = blockIdx.y*128, n0 = blockIdx.x*128;

    const uint4 *Ag, *Alg, *Bg, *Blg;
    if      (which==0){ Ag=(const uint4*)g_xqh; Alg=(const uint4*)g_xql; Bg=(const uint4*)g_wqh; Blg=(const uint4*)g_wql; }
    else if (which==1){ Ag=(const uint4*)g_xkh; Alg=(const uint4*)g_xkl; Bg=(const uint4*)g_wkh; Blg=(const uint4*)g_wkl; }
    else if (which==2){ Ag=(const uint4*)g_xvh; Alg=(const uint4*)g_xvl; Bg=(const uint4*)g_wvh; Blg=(const uint4*)g_wvl; }
    else              { Ag=(const uint4*)g_oh;  Alg=(const uint4*)g_ol;  Bg=(const uint4*)g_wfh; Blg=(const uint4*)g_wfl; }

    auto fill = [&](int s, int k0){
        char* st = sm + s*G_STG;
        __nv_bfloat16* Ah_s = (__nv_bfloat16*)st;
        __nv_bfloat16* Al_s = (__nv_bfloat16*)(st + 10240);
        __nv_bfloat16* Bh_s = (__nv_bfloat16*)(st + 20480);
        __nv_bfloat16* Bl_s = (__nv_bfloat16*)(st + 30720);
        #pragma unroll
        for (int c = tid; c < 512; c += 256) {
            int r = c>>2, q = c&3;
            size_t aidx;
            if (which == 3) {
                int m = m0 + r, b = m>>11, s2 = m&(SEQ-1), h = k0>>6;
                aidx = ((size_t)(b*NH + h)*SEQ + s2)*8 + ((k0&63)>>3) + q;
            } else {
                aidx = (size_t)(m0 + r)*128 + (k0>>3) + q;
            }
            cp16(&Ah_s[r*40 + q*8], &Ag[aidx]);
            cp16(&Al_s[r*40 + q*8], &Alg[aidx]);
            size_t bidx = (size_t)(n0 + r)*128 + (k0>>3) + q;
            cp16(&Bh_s[r*40 + q*8], &Bg[bidx]);
            cp16(&Bl_s[r*40 + q*8], &Blg[bidx]);
        }
    };

    FragC acc[2][4];
    #pragma unroll
    for (int i = 0; i < 2; i++)
        #pragma unroll
        for (int j = 0; j < 4; j++) wmma::fill_fragment(acc[i][j], 0.0f);

    fill(0, 0); cp_commit();
    for (int it = 0; it < 32; ++it) {
        if (it < 31) { fill((it+1)&1, (it+1)*32); cp_commit(); cp_wait<1>(); }
        else cp_wait<0>();
        __syncthreads();
        char* st = sm + (it&1)*G_STG;
        __nv_bfloat16* Ah_s = (__nv_bfloat16*)st;
        __nv_bfloat16* Al_s = (__nv_bfloat16*)(st + 10240);
        __nv_bfloat16* Bh_s = (__nv_bfloat16*)(st + 20480);
        __nv_bfloat16* Bl_s = (__nv_bfloat16*)(st + 30720);
        #pragma unroll
        for (int ks = 0; ks < 32; ks += 16) {
            FragA ah[2], al[2];
            #pragma unroll
            for (int i = 0; i < 2; i++) {
                wmma::load_matrix_sync(ah[i], &Ah_s[(wm*32 + i*16)*40 + ks], 40);
                wmma::load_matrix_sync(al[i], &Al_s[(wm*32 + i*16)*40 + ks], 40);
            }
            #pragma unroll
            for (int j = 0; j < 4; j++) {
                FragBc bh, bl;
                wmma::load_matrix_sync(bh, &Bh_s[(wn*64 + j*16)*40 + ks], 40);
                wmma::load_matrix_sync(bl, &Bl_s[(wn*64 + j*16)*40 + ks], 40);
                #pragma unroll
                for (int i = 0; i < 2; i++) {
                    wmma::mma_sync(acc[i][j], ah[i], bh, acc[i][j]);
                    wmma::mma_sync(acc[i][j], ah[i], bl, acc[i][j]);
                    wmma::mma_sync(acc[i][j], al[i], bh, acc[i][j]);
                }
            }
        }
        __syncthreads();
    }

    if (which == 3) {
        #pragma unroll
        for (int i = 0; i < 2; i++)
            #pragma unroll
            for (int j = 0; j < 4; j++)
                wmma::store_matrix_sync(&g_y[(size_t)(m0 + wm*32 + i*16)*DM + n0 + wn*64 + j*16],
                                        acc[i][j], DM, wmma::mem_row_major);
    } else {
        float* Cst = (float*)sm;   // 128 x 68 overlay
        __nv_bfloat16 *oh, *ol;
        if      (which == 0){ oh = g_qh; ol = g_ql; }
        else if (which == 1){ oh = g_kh; ol = g_kl; }
        else               { oh = g_vh; ol = g_vl; }
        for (int half = 0; half < 2; half++) {
            if (wn == half) {
                #pragma unroll
                for (int i = 0; i < 2; i++)
                    #pragma unroll
                    for (int j = 0; j < 4; j++)
                        wmma::store_matrix_sync(&Cst[(wm*32 + i*16)*68 + j*16],
                                                acc[i][j], 68, wmma::mem_row_major);
            }
            __syncthreads();
            int r = tid>>1, cbase = (tid&1)*32;
            int m = m0 + r, b = m>>11, s = m&(SEQ-1);
            int h = (n0 + half*64) >> 6;
            size_t base = ((size_t)(b*NH + h)*SEQ + s)*DQ + cbase;
            #pragma unroll
            for (int c = 0; c < 32; c += 2)
                split_store(oh, ol, base + c, Cst[r*68 + cbase + c], Cst[r*68 + cbase + c + 1]);
            __syncthreads();
        }
    }
}

// ---------------- scores (wmma, cp.async 2-stage K): raw S + online (m,l) ------------
#define SC_QH   0
#define SC_QL   18432
#define SC_K    36864            // stage s: +s*18432; KH +0 (9216), KL +9216
#define SC_SST  73728            // 128*68*4 = 34816
#define SC_NM   108544
#define SC_PMAX 109056
#define SC_PSUM 110080
#define SC_RM   111104
#define SC_BYTES 111616

__global__ void __launch_bounds__(256) scores_wmma(float* __restrict__ a_out)
{
    extern __shared__ __align__(16) char sm[];
    __nv_bfloat16* Qh_s = (__nv_bfloat16*)(sm + SC_QH);
    __nv_bfloat16* Ql_s = (__nv_bfloat16*)(sm + SC_QL);
    float* Sst  = (float*)(sm + SC_SST);
    float* pmax = (float*)(sm + SC_PMAX);
    float* psum = (float*)(sm + SC_PSUM);
    float* rm_s = (float*)(sm + SC_RM);

    const int tid = threadIdx.x, wid = tid>>5;
    const int wm = wid & 3, wn = wid >> 2;
    const int bh = blockIdx.y, q0 = blockIdx.x*128;
    float* Sp = a_out + (size_t)bh*SEQ*SEQ;
    const uint4* qh = (const uint4*)g_qh + (size_t)bh*SEQ*8;
    const uint4* ql = (const uint4*)g_ql + (size_t)bh*SEQ*8;
    const uint4* kh = (const uint4*)g_kh + (size_t)bh*SEQ*8;
    const uint4* kl = (const uint4*)g_kl + (size_t)bh*SEQ*8;

    auto fillK = [&](int s, int kv0){
        __nv_bfloat16* Kh_s = (__nv_bfloat16*)(sm + SC_K + s*18432);
        __nv_bfloat16* Kl_s = (__nv_bfloat16*)(sm + SC_K + s*18432 + 9216);
        #pragma unroll
        for (int c = tid; c < 512; c += 256) {
            int r = c>>3, q = c&7;
            cp16(&Kh_s[r*72 + q*8], &kh[(size_t)(kv0 + r)*8 + q]);
            cp16(&Kl_s[r*72 + q*8], &kl[(size_t)(kv0 + r)*8 + q]);
        }
    };

    for (int c = tid; c < 1024; c += 256) {
        int r = c>>3, q = c&7;
        *(uint4*)&Qh_s[r*72 + q*8] = qh[(size_t)(q0 + r)*8 + q];
        *(uint4*)&Ql_s[r*72 + q*8] = ql[(size_t)(q0 + r)*8 + q];
    }
    if (tid < 128) rm_s[tid] = NEG_INF;
    float run_l = 0.f;
    const int rr = tid & 127, rhalf = tid >> 7;

    fillK(0, 0); cp_commit();
    for (int t = 0; t < 32; t++) {
        const int kv0 = t*64;
        if (t < 31) { fillK((t+1)&1, kv0 + 64); cp_commit(); cp_wait<1>(); }
        else cp_wait<0>();
        __syncthreads();

        __nv_bfloat16* Kh_s = (__nv_bfloat16*)(sm + SC_K + (t&1)*18432);
        __nv_bfloat16* Kl_s = (__nv_bfloat16*)(sm + SC_K + (t&1)*18432 + 9216);

        FragC acc[2][2];
        #pragma unroll
        for (int i = 0; i < 2; i++)
            #pragma unroll
            for (int j = 0; j < 2; j++) wmma::fill_fragment(acc[i][j], 0.0f);
        #pragma unroll
        for (int ks = 0; ks < 64; ks += 16) {
            FragA ah[2], al[2];
            #pragma unroll
            for (int i = 0; i < 2; i++) {
                wmma::load_matrix_sync(ah[i], &Qh_s[(wm*32 + i*16)*72 + ks], 72);
                wmma::load_matrix_sync(al[i], &Ql_s[(wm*32 + i*16)*72 + ks], 72);
            }
            #pragma unroll
            for (int j = 0; j < 2; j++) {
                FragBc bh2, bl2;
                wmma::load_matrix_sync(bh2, &Kh_s[(wn*32 + j*16)*72 + ks], 72);
                wmma::load_matrix_sync(bl2, &Kl_s[(wn*32 + j*16)*72 + ks], 72);
                #pragma unroll
                for (int i = 0; i < 2; i++) {
                    wmma::mma_sync(acc[i][j], ah[i], bh2, acc[i][j]);
                    wmma::mma_sync(acc[i][j], ah[i], bl2, acc[i][j]);
                    wmma::mma_sync(acc[i][j], al[i], bh2, acc[i][j]);
                }
            }
        }
        #pragma unroll
        for (int i = 0; i < 2; i++)
            #pragma unroll
            for (int j = 0; j < 2; j++)
                wmma::store_matrix_sync(&Sst[(wm*32 + i*16)*68 + wn*32 + j*16],
                                        acc[i][j], 68, wmma::mem_row_major);
        __syncthreads();

        // raw-S write (coalesced) + half-row max
        for (int idx = tid; idx < 2048; idx += 256) {
            int r = idx>>4, c4 = (idx&15)*4;
            *(float4*)(Sp + (size_t)(q0 + r)*SEQ + kv0 + c4) = *(float4*)&Sst[r*68 + c4];
        }
        float hm = NEG_INF;
        #pragma unroll
        for (int i = 0; i < 8; i++) {
            float4 v = *(float4*)&Sst[rr*68 + rhalf*32 + i*4];
            hm = fmaxf(hm, fmaxf(fmaxf(v.x, v.y), fmaxf(v.z, v.w)));
        }
        pmax[rr*2 + rhalf] = hm;
        __syncthreads();

        const float nm = fmaxf(rm_s[rr], fmaxf(pmax[rr*2], pmax[rr*2 + 1]));
        float es = 0.f;
        #pragma unroll
        for (int i = 0; i < 8; i++) {
            float4 v = *(float4*)&Sst[rr*68 + rhalf*32 + i*4];
            es += __expf(v.x - nm) + __expf(v.y - nm) + __expf(v.z - nm) + __expf(v.w - nm);
        }
        psum[rr*2 + rhalf] = es;
        __syncthreads();

        if (tid < 128) {
            const float om = rm_s[tid];
            const float nm2 = fmaxf(om, fmaxf(pmax[tid*2], pmax[tid*2 + 1]));
            run_l = run_l * __expf(om - nm2) + psum[tid*2] + psum[tid*2 + 1];
            rm_s[tid] = nm2;
        }
    }
    if (tid < 128) {
        g_m[(size_t)bh*SEQ + q0 + tid] = rm_s[tid];
        g_l[(size_t)bh*SEQ + q0 + tid] = run_l;
    }
}

// ---------------- AV (wmma, cp.async 2-stage V): probs in-place + O = P V -----------
#define AV_PH   0
#define AV_PL   18432
#define AV_V    36864           // stage s: +s*18432; VH +0, VL +9216
#define AV_M    73728
#define AV_IL   74240
#define AV_BYTES 74752

__global__ void __launch_bounds__(256) av_wmma(float* __restrict__ a_out)
{
    extern __shared__ __align__(16) char sm[];
    __nv_bfloat16* Ph_s = (__nv_bfloat16*)(sm + AV_PH);
    __nv_bfloat16* Pl_s = (__nv_bfloat16*)(sm + AV_PL);
    float* sm_m  = (float*)(sm + AV_M);
    float* sm_il = (float*)(sm + AV_IL);

    const int tid = threadIdx.x, wid = tid>>5;
    const int wm = wid & 3, wn = wid >> 2;
    const int bh = blockIdx.y, q0 = blockIdx.x*128;
    float* Sp = a_out + (size_t)bh*SEQ*SEQ;
    const uint4* vh = (const uint4*)g_vh + (size_t)bh*SEQ*8;
    const uint4* vl = (const uint4*)g_vl + (size_t)bh*SEQ*8;

    auto fillV = [&](int s, int kv0){
        __nv_bfloat16* Vh_s = (__nv_bfloat16*)(sm + AV_V + s*18432);
        __nv_bfloat16* Vl_s = (__nv_bfloat16*)(sm + AV_V + s*18432 + 9216);
        #pragma unroll
        for (int c = tid; c < 512; c += 256) {
            int r = c>>3, q = c&7;
            cp16(&Vh_s[r*72 + q*8], &vh[(size_t)(kv0 + r)*8 + q]);
            cp16(&Vl_s[r*72 + q*8], &vl[(size_t)(kv0 + r)*8 + q]);
        }
    };

    if (tid < 128) {
        sm_m[tid]  = g_m[(size_t)bh*SEQ + q0 + tid];
        sm_il[tid] = 1.0f / g_l[(size_t)bh*SEQ + q0 + tid];
    }
    __syncthreads();

    FragC acc[2][2];
    #pragma unroll
    for (int i = 0; i < 2; i++)
        #pragma unroll
        for (int j = 0; j < 2; j++) wmma::fill_fragment(acc[i][j], 0.0f);

    fillV(0, 0); cp_commit();
    for (int t = 0; t < 32; t++) {
        const int kv0 = t*64;
        if (t < 31) { fillV((t+1)&1, kv0 + 64); cp_commit(); }

        // normalize S -> probs (write back) + split into Ph/Pl (overlaps V cp.async)
        #pragma unroll
        for (int p = 0; p < 4; p++) {
            int r  = p*32 + (tid>>3);
            int c0 = (tid&7)*4;
            float m = sm_m[r], il = sm_il[r];
            #pragma unroll
            for (int h2 = 0; h2 < 2; h2++) {
                int c = c0 + h2*32;
                float* sp = Sp + (size_t)(q0 + r)*SEQ + kv0 + c;
                float4 v = *(const float4*)sp;
                float4 pr;
                pr.x = __expf(v.x - m)*il; pr.y = __expf(v.y - m)*il;
                pr.z = __expf(v.z - m)*il; pr.w = __expf(v.w - m)*il;
                *(float4*)sp = pr;
                split_store(Ph_s, Pl_s, (size_t)r*72 + c,     pr.x, pr.y);
                split_store(Ph_s, Pl_s, (size_t)r*72 + c + 2, pr.z, pr.w);
            }
        }
        if (t < 31) cp_wait<1>(); else cp_wait<0>();
        __syncthreads();

        __nv_bfloat16* Vh_s = (__nv_bfloat16*)(sm + AV_V + (t&1)*18432);
        __nv_bfloat16* Vl_s = (__nv_bfloat16*)(sm + AV_V + (t&1)*18432 + 9216);
        #pragma unroll
        for (int ks = 0; ks < 64; ks += 16) {
            FragA ah[2], al[2];
            #pragma unroll
            for (int i = 0; i < 2; i++) {
                wmma::load_matrix_sync(ah[i], &Ph_s[(wm*32 + i*16)*72 + ks], 72);
                wmma::load_matrix_sync(al[i], &Pl_s[(wm*32 + i*16)*72 + ks], 72);
            }
            #pragma unroll
            for (int j = 0; j < 2; j++) {
                FragBr bh2, bl2;
                wmma::load_matrix_sync(bh2, &Vh_s[ks*72 + wn*32 + j*16], 72);
                wmma::load_matrix_sync(bl2, &Vl_s[ks*72 + wn*32 + j*16], 72);
                #pragma unroll
                for (int i = 0; i < 2; i++) {
                    wmma::mma_sync(acc[i][j], ah[i], bh2, acc[i][j]);
                    wmma::mma_sync(acc[i][j], ah[i], bl2, acc[i][j]);
                    wmma::mma_sync(acc[i][j], al[i], bh2, acc[i][j]);
                }
            }
        }
        __syncthreads();
    }

    float* Ost = (float*)(sm + AV_PH);   // overlay Ph/Pl: 128*68*4 = 34816 <= 36864
    #pragma unroll
    for (int i = 0; i < 2; i++)
        #pragma unroll
        for (int j = 0; j < 2; j++)
            wmma::store_matrix_sync(&Ost[(wm*32 + i*16)*68 + wn*32 + j*16],
                                    acc[i][j], 68, wmma::mem_row_major);
    __syncthreads();
    {
        int r = tid>>1, cbase = (tid&1)*32;
        size_t base = ((size_t)bh*SEQ + q0 + r)*DQ + cbase;
        #pragma unroll
        for (int c = 0; c < 32; c += 2)
            split_store(g_oh, g_ol, base + c, Ost[r*68 + cbase + c], Ost[r*68 + cbase + c + 1]);
    }
}

// ---------------- residual + LayerNorm ----------------
__global__ void __launch_bounds__(256) ln_kernel(const float* __restrict__ xq,
                                                 float* __restrict__ out)
{
    const int r = blockIdx.x;
    const int t = threadIdx.x;
    float4 a = ((const float4*)(g_y + (size_t)r*DM))[t];
    float4 b = ((const float4*)(xq  + (size_t)r*DM))[t];
    float z0 = a.x + b.x, z1 = a.y + b.y, z2 = a.z + b.z, z3 = a.w + b.w;
    float s = z0 + z1 + z2 + z3;
    float q = z0*z0 + z1*z1 + z2*z2 + z3*z3;

    __shared__ float red[2][8];
    #pragma unroll
    for (int o = 16; o; o >>= 1) {
        s += __shfl_xor_sync(0xffffffffu, s, o);
        q += __shfl_xor_sync(0xffffffffu, q, o);
    }
    int w = t >> 5, l = t & 31;
    if (l == 0) { red[0][w] = s; red[1][w] = q; }
    __syncthreads();
    float S = 0.f, Q = 0.f;
    #pragma unroll
    for (int i = 0; i < 8; i++) { S += red[0][i]; Q += red[1][i]; }
    float mu  = S * (1.0f / DM);
    float var = Q * (1.0f / DM) - mu * mu;
    float inv = rsqrtf(var + 1e-5f);
    float4 o;
    o.x = (z0 - mu) * inv; o.y = (z1 - mu) * inv;
    o.z = (z2 - mu) * inv; o.w = (z3 - mu) * inv;
    ((float4*)(out + (size_t)r*DM))[t] = o;
}

// ---------------- launch ----------------
extern "C" void kernel_launch(void* const* d_in, const int* in_sizes, int n_in,
                              void* d_out, int out_size)
{
    (void)in_sizes; (void)n_in; (void)out_size;
    const float* xq  = (const float*)d_in[0];
    const float* xk  = (const float*)d_in[1];
    const float* xv  = (const float*)d_in[2];
    const float* WQ  = (const float*)d_in[3];
    const float* WK  = (const float*)d_in[4];
    const float* WV  = (const float*)d_in[5];
    const float* Wfc = (const float*)d_in[6];

    float* a_out = (float*)d_out;                         // [2,16,2048,2048]
    float* o_out = (float*)d_out + (size_t)BHN*SEQ*SEQ;   // [2,2048,1024]

    cudaFuncSetAttribute(gemm_wmma,   cudaFuncAttributeMaxDynamicSharedMemorySize, G_BYTES);
    cudaFuncSetAttribute(scores_wmma, cudaFuncAttributeMaxDynamicSharedMemorySize, SC_BYTES);
    cudaFuncSetAttribute(av_wmma,     cudaFuncAttributeMaxDynamicSharedMemorySize, AV_BYTES);

    dim3 gg(DM/128, (BS*SEQ)/128);   // (8, 32)

    // launch order puts av_wmma at index 5 so ncu (-s 5 -c 1) profiles it
    split_all<<<16384, 256>>>((const float4*)xq, (const float4*)xk, (const float4*)xv,
                              (const float4*)WQ, (const float4*)WK, (const float4*)WV,
                              (const float4*)Wfc);                       // 0
    gemm_wmma<<<gg, 256, G_BYTES>>>(0);                                  // 1  Q
    gemm_wmma<<<gg, 256, G_BYTES>>>(1);                                  // 2  K
    scores_wmma<<<dim3(SEQ/128, BHN), 256, SC_BYTES>>>(a_out);           // 3
    gemm_wmma<<<gg, 256, G_BYTES>>>(2);                                  // 4  V
    av_wmma<<<dim3(SEQ/128, BHN), 256, AV_BYTES>>>(a_out);               // 5  <- profiled
    gemm_wmma<<<gg, 256, G_BYTES>>>(3);                                  // 6  fc
    ln_kernel<<<BS*SEQ, 256>>>(xq, o_out);                               // 7
}